// round 1
// baseline (speedup 1.0000x reference)
#include <cuda_runtime.h>

#define D_MODEL 1024
#define HEADS   16
#define HD      64
#define BB      2
#define TT      2048
#define MTOT    (BB*TT)
#define AP      68            // padded smem row stride (floats) for attention tiles
#define ATTN_SMEM (4*64*AP*4) // 4 tiles of 64xAP floats = 69632 bytes

// Scratch (device globals: no allocations allowed)
__device__ float g_Q[(size_t)MTOT * D_MODEL];
__device__ float g_K[(size_t)MTOT * D_MODEL];
__device__ float g_V[(size_t)MTOT * D_MODEL];
__device__ float g_A[(size_t)MTOT * D_MODEL];
__device__ float g_scl[MTOT];

// ---------------------------------------------------------------------------
// GEMM body: C = A @ W^T + bias. A:(4096x1024) row-major, W:(1024x1024) row-major
// (torch Linear weight: both operands K-contiguous). 128x128 tile, BK=8,
// 8x8 microtile per thread, 256 threads.
// ---------------------------------------------------------------------------
__device__ __forceinline__ void gemm_body(
    const float* __restrict__ A, const float* __restrict__ W,
    const float* __restrict__ bias, float* __restrict__ C)
{
    __shared__ float As[8][132];  // padded: conflict-free stores & float4 loads
    __shared__ float Ws[8][132];
    const int bm = blockIdx.y * 128;
    const int bn = blockIdx.x * 128;
    const int tid  = threadIdx.x;
    const int tr   = tid >> 4;        // 0..15 (row group)
    const int tc   = tid & 15;        // 0..15 (col group)
    const int la_r = tid >> 1;        // 0..127
    const int la_c = (tid & 1) * 4;   // 0 or 4

    const float* Ag = A + (size_t)(bm + la_r) * D_MODEL + la_c;
    const float* Wg = W + (size_t)(bn + la_r) * D_MODEL + la_c;

    float acc[8][8];
#pragma unroll
    for (int i = 0; i < 8; i++)
#pragma unroll
        for (int j = 0; j < 8; j++) acc[i][j] = 0.f;

    for (int k0 = 0; k0 < D_MODEL; k0 += 8) {
        float4 a4 = *(const float4*)(Ag + k0);
        float4 w4 = *(const float4*)(Wg + k0);
        As[la_c+0][la_r] = a4.x; As[la_c+1][la_r] = a4.y;
        As[la_c+2][la_r] = a4.z; As[la_c+3][la_r] = a4.w;
        Ws[la_c+0][la_r] = w4.x; Ws[la_c+1][la_r] = w4.y;
        Ws[la_c+2][la_r] = w4.z; Ws[la_c+3][la_r] = w4.w;
        __syncthreads();
#pragma unroll
        for (int kk = 0; kk < 8; kk++) {
            float ar[8], wr[8];
            *(float4*)&ar[0] = *(const float4*)&As[kk][tr*8];
            *(float4*)&ar[4] = *(const float4*)&As[kk][tr*8 + 4];
            *(float4*)&wr[0] = *(const float4*)&Ws[kk][tc*8];
            *(float4*)&wr[4] = *(const float4*)&Ws[kk][tc*8 + 4];
#pragma unroll
            for (int i = 0; i < 8; i++)
#pragma unroll
                for (int j = 0; j < 8; j++)
                    acc[i][j] += ar[i] * wr[j];
        }
        __syncthreads();
    }

    float br[8];
    *(float4*)&br[0] = *(const float4*)(bias + bn + tc*8);
    *(float4*)&br[4] = *(const float4*)(bias + bn + tc*8 + 4);
#pragma unroll
    for (int i = 0; i < 8; i++) {
        size_t m = (size_t)(bm + tr*8 + i);
        float* cp = C + m * D_MODEL + bn + tc*8;
        *(float4*)(cp)     = make_float4(acc[i][0]+br[0], acc[i][1]+br[1],
                                         acc[i][2]+br[2], acc[i][3]+br[3]);
        *(float4*)(cp + 4) = make_float4(acc[i][4]+br[4], acc[i][5]+br[5],
                                         acc[i][6]+br[6], acc[i][7]+br[7]);
    }
}

__global__ __launch_bounds__(256, 2) void qkv_gemm_kernel(
    const float* __restrict__ q_in, const float* __restrict__ k_in,
    const float* __restrict__ v_in,
    const float* __restrict__ Wq, const float* __restrict__ bq,
    const float* __restrict__ Wk, const float* __restrict__ bk,
    const float* __restrict__ Wv, const float* __restrict__ bv)
{
    const float *A, *W, *bias; float* C;
    if (blockIdx.z == 0)      { A = q_in; W = Wq; bias = bq; C = g_Q; }
    else if (blockIdx.z == 1) { A = k_in; W = Wk; bias = bk; C = g_K; }
    else                      { A = v_in; W = Wv; bias = bv; C = g_V; }
    gemm_body(A, W, bias, C);
}

__global__ __launch_bounds__(256, 2) void out_gemm_kernel(
    const float* __restrict__ Wo, const float* __restrict__ bo,
    float* __restrict__ out)
{
    gemm_body(g_A, Wo, bo, out);
}

// ---------------------------------------------------------------------------
// Per-query-token score scale.
// Softmax shift invariance kills the logvar / (1-phi) additive terms; the
// divide by max(mean(phi),1e-6) is a positive per-row scale. Combined with
// 1/sqrt(64): scale = 1 / (8 * max(mean(phi), 1e-6)).
// ---------------------------------------------------------------------------
__global__ void scale_kernel(const float* __restrict__ phi)
{
    int i = blockIdx.x * 256 + threadIdx.x;
    if (i < MTOT) {
        const float* p = phi + (size_t)i * 8;
        float s = 0.f;
#pragma unroll
        for (int f = 0; f < 8; f++) s += p[f];
        float ph = s * 0.125f;
        g_scl[i] = 1.0f / (8.0f * fmaxf(ph, 1e-6f));
    }
}

// ---------------------------------------------------------------------------
// Flash attention, fp32. One block = one (b, h, 64-query tile).
// 256 threads as 16x16 grid; each thread owns a 4x4 microtile of the 64x64
// S tile / 64x64 O tile. Online softmax; row groups of 16 lanes reduce via
// shfl.xor (lane layout: ty = tid>>4, tx = tid&15 -> 16 consecutive lanes).
// ---------------------------------------------------------------------------
__global__ __launch_bounds__(256, 2) void attn_kernel()
{
    extern __shared__ float sm[];
    float* Qs = sm;               // [64][AP]  Qs[kk][row]   (K-dim major)
    float* Ks = Qs + 64*AP;       // [64][AP]  Ks[kk][col]   (K-dim major)
    float* Vs = Ks + 64*AP;       // [64][AP]  Vs[key][dim]
    float* Ps = Vs + 64*AP;       // [64][AP]  Ps[row][key]

    const int b  = blockIdx.z, h = blockIdx.y;
    const int q0 = blockIdx.x * 64;
    const int tid = threadIdx.x;
    const int lr  = tid & 63;     // loader row (token index within tile)
    const int qtr = tid >> 6;     // loader 16-col slice
    const int ty  = tid >> 4;     // 0..15
    const int tx  = tid & 15;     // 0..15

    const size_t hoff = (size_t)h * HD;

    // Load Q tile transposed into smem (once)
    {
        const float* Qg = g_Q + ((size_t)(b*TT + q0 + lr)) * D_MODEL + hoff + qtr*16;
#pragma unroll
        for (int u = 0; u < 4; u++) {
            float4 v = *(const float4*)(Qg + u*4);
            int c = qtr*16 + u*4;
            Qs[(c+0)*AP + lr] = v.x; Qs[(c+1)*AP + lr] = v.y;
            Qs[(c+2)*AP + lr] = v.z; Qs[(c+3)*AP + lr] = v.w;
        }
    }

    float rs[4], m[4], l[4], o[4][4];
#pragma unroll
    for (int i = 0; i < 4; i++) {
        rs[i] = g_scl[b*TT + q0 + ty*4 + i];
        m[i] = -1e30f; l[i] = 0.f;
#pragma unroll
        for (int j = 0; j < 4; j++) o[i][j] = 0.f;
    }

    for (int kt = 0; kt < TT/64; kt++) {
        __syncthreads();   // protect Ks/Vs/Ps from previous iteration's readers
        const int k0 = kt * 64;
        {
            const float* Kg = g_K + ((size_t)(b*TT + k0 + lr)) * D_MODEL + hoff + qtr*16;
            const float* Vg = g_V + ((size_t)(b*TT + k0 + lr)) * D_MODEL + hoff + qtr*16;
#pragma unroll
            for (int u = 0; u < 4; u++) {
                int c = qtr*16 + u*4;
                float4 kv = *(const float4*)(Kg + u*4);
                Ks[(c+0)*AP + lr] = kv.x; Ks[(c+1)*AP + lr] = kv.y;
                Ks[(c+2)*AP + lr] = kv.z; Ks[(c+3)*AP + lr] = kv.w;
                float4 vv = *(const float4*)(Vg + u*4);
                *(float4*)&Vs[lr*AP + c] = vv;
            }
        }
        __syncthreads();

        // S = Q K^T  (4x4 microtile)
        float s[4][4];
#pragma unroll
        for (int i = 0; i < 4; i++)
#pragma unroll
            for (int j = 0; j < 4; j++) s[i][j] = 0.f;

#pragma unroll 16
        for (int kk = 0; kk < 64; kk++) {
            float4 qv = *(const float4*)&Qs[kk*AP + ty*4];
            float4 kv = *(const float4*)&Ks[kk*AP + tx*4];
            s[0][0] += qv.x*kv.x; s[0][1] += qv.x*kv.y; s[0][2] += qv.x*kv.z; s[0][3] += qv.x*kv.w;
            s[1][0] += qv.y*kv.x; s[1][1] += qv.y*kv.y; s[1][2] += qv.y*kv.z; s[1][3] += qv.y*kv.w;
            s[2][0] += qv.z*kv.x; s[2][1] += qv.z*kv.y; s[2][2] += qv.z*kv.z; s[2][3] += qv.z*kv.w;
            s[3][0] += qv.w*kv.x; s[3][1] += qv.w*kv.y; s[3][2] += qv.w*kv.z; s[3][3] += qv.w*kv.w;
        }

        // Per-row scale + online softmax (reduce over 16 lanes of the row group)
#pragma unroll
        for (int i = 0; i < 4; i++) {
#pragma unroll
            for (int j = 0; j < 4; j++) s[i][j] *= rs[i];
            float tm = fmaxf(fmaxf(s[i][0], s[i][1]), fmaxf(s[i][2], s[i][3]));
#pragma unroll
            for (int off = 8; off >= 1; off >>= 1)
                tm = fmaxf(tm, __shfl_xor_sync(0xffffffffu, tm, off));
            float mn = fmaxf(m[i], tm);
            float corr = __expf(m[i] - mn);
            m[i] = mn;
            float ts = 0.f;
#pragma unroll
            for (int j = 0; j < 4; j++) { s[i][j] = __expf(s[i][j] - mn); ts += s[i][j]; }
#pragma unroll
            for (int off = 8; off >= 1; off >>= 1)
                ts += __shfl_xor_sync(0xffffffffu, ts, off);
            l[i] = l[i]*corr + ts;
#pragma unroll
            for (int j = 0; j < 4; j++) o[i][j] *= corr;
            *(float4*)&Ps[(ty*4+i)*AP + tx*4] = make_float4(s[i][0], s[i][1], s[i][2], s[i][3]);
        }
        __syncthreads();

        // O += P V
#pragma unroll 16
        for (int kk = 0; kk < 64; kk++) {
            float4 vv = *(const float4*)&Vs[kk*AP + tx*4];
            float p0 = Ps[(ty*4+0)*AP + kk];
            float p1 = Ps[(ty*4+1)*AP + kk];
            float p2 = Ps[(ty*4+2)*AP + kk];
            float p3 = Ps[(ty*4+3)*AP + kk];
            o[0][0] += p0*vv.x; o[0][1] += p0*vv.y; o[0][2] += p0*vv.z; o[0][3] += p0*vv.w;
            o[1][0] += p1*vv.x; o[1][1] += p1*vv.y; o[1][2] += p1*vv.z; o[1][3] += p1*vv.w;
            o[2][0] += p2*vv.x; o[2][1] += p2*vv.y; o[2][2] += p2*vv.z; o[2][3] += p2*vv.w;
            o[3][0] += p3*vv.x; o[3][1] += p3*vv.y; o[3][2] += p3*vv.z; o[3][3] += p3*vv.w;
        }
    }

    // Epilogue: normalize and write head output
#pragma unroll
    for (int i = 0; i < 4; i++) {
        float inv = 1.0f / l[i];
        float* op = g_A + ((size_t)(b*TT + q0 + ty*4 + i)) * D_MODEL + hoff + tx*4;
        *(float4*)op = make_float4(o[i][0]*inv, o[i][1]*inv, o[i][2]*inv, o[i][3]*inv);
    }
}

// ---------------------------------------------------------------------------
extern "C" void kernel_launch(void* const* d_in, const int* in_sizes, int n_in,
                              void* d_out, int out_size)
{
    const float* query = (const float*)d_in[0];
    const float* key   = (const float*)d_in[1];
    const float* value = (const float*)d_in[2];
    const float* phi   = (const float*)d_in[3];
    // d_in[4] logvar, d_in[13] w_sigma, d_in[14] w_phi: cancel under softmax
    const float* Wq = (const float*)d_in[5];
    const float* bq = (const float*)d_in[6];
    const float* Wk = (const float*)d_in[7];
    const float* bk = (const float*)d_in[8];
    const float* Wv = (const float*)d_in[9];
    const float* bv = (const float*)d_in[10];
    const float* Wo = (const float*)d_in[11];
    const float* bo = (const float*)d_in[12];
    float* out = (float*)d_out;

    cudaFuncSetAttribute(attn_kernel, cudaFuncAttributeMaxDynamicSharedMemorySize,
                         ATTN_SMEM);

    qkv_gemm_kernel<<<dim3(D_MODEL/128, MTOT/128, 3), 256>>>(
        query, key, value, Wq, bq, Wk, bk, Wv, bv);
    scale_kernel<<<(MTOT + 255)/256, 256>>>(phi);
    attn_kernel<<<dim3(TT/64, HEADS, BB), 256, ATTN_SMEM>>>();
    out_gemm_kernel<<<dim3(D_MODEL/128, MTOT/128, 1), 256>>>(Wo, bo, out);
}

// round 4
// speedup vs baseline: 1.3813x; 1.3813x over previous
#include <cuda_runtime.h>
#include <cuda_bf16.h>
#include <cstdint>

#define D_MODEL 1024
#define HEADS   16
#define HD      64
#define BB      2
#define TT      2048
#define MTOT    (BB*TT)

// ---------------- attention (SIMT fp32, unchanged) ----------------
#define AP      68
#define ATTN_SMEM (4*64*AP*4)

// ---------------- HMMA (mma.sync) GEMM config ----------------
// 128x128 CTA tile, KC=32 k-chunk, 8 warps in 2x4 grid, warp tile 64x32.
// Split-bf16: x = hi + lo; C += Ahi*Whi + Ahi*Wlo + Alo*Whi.
#define KC      32
#define NCHUNK  (D_MODEL/KC)       // 32
#define RSB     80                 // smem row stride bytes (32 bf16 + 16B pad -> ldmatrix conflict-free)
#define OPB     (128*RSB)          // one operand tile: 10240 B
#define STAGEB  (4*OPB)            // Ahi, Alo, Whi, Wlo = 40960 B
#define GEMM_SMEM (2*STAGEB)       // 2 stages = 81920 B

// Scratch (device globals: allocations forbidden)
__device__ float g_Q[(size_t)MTOT * D_MODEL];
__device__ float g_K[(size_t)MTOT * D_MODEL];
__device__ float g_V[(size_t)MTOT * D_MODEL];
__device__ float g_A[(size_t)MTOT * D_MODEL];
__device__ float g_scl[MTOT];

// ---------------- helpers ----------------
__device__ __forceinline__ uint32_t smem_u32(const void* p) {
    uint32_t a;
    asm("{ .reg .u64 t; cvta.to.shared.u64 t, %1; cvt.u32.u64 %0, t; }" : "=r"(a) : "l"(p));
    return a;
}
__device__ __forceinline__ void ldsm4(uint32_t* r, uint32_t addr) {
    asm volatile("ldmatrix.sync.aligned.m8n8.x4.shared.b16 {%0,%1,%2,%3}, [%4];"
                 : "=r"(r[0]), "=r"(r[1]), "=r"(r[2]), "=r"(r[3]) : "r"(addr));
}
__device__ __forceinline__ void mma_bf16(float* d, const uint32_t* a, const uint32_t* b) {
    asm volatile("mma.sync.aligned.m16n8k16.row.col.f32.bf16.bf16.f32 "
                 "{%0,%1,%2,%3}, {%4,%5,%6,%7}, {%8,%9}, {%0,%1,%2,%3};"
                 : "+f"(d[0]), "+f"(d[1]), "+f"(d[2]), "+f"(d[3])
                 : "r"(a[0]), "r"(a[1]), "r"(a[2]), "r"(a[3]), "r"(b[0]), "r"(b[1]));
}
__device__ __forceinline__ uint32_t bits(const __nv_bfloat162& h) {
    return *reinterpret_cast<const uint32_t*>(&h);
}
// 8 fp32 -> 8 bf16 hi (16B) + 8 bf16 lo (16B)
__device__ __forceinline__ void cvt_store(char* hip, char* lop,
                                          const float4& f0, const float4& f1) {
    __nv_bfloat162 h0 = __floats2bfloat162_rn(f0.x, f0.y);
    __nv_bfloat162 h1 = __floats2bfloat162_rn(f0.z, f0.w);
    __nv_bfloat162 h2 = __floats2bfloat162_rn(f1.x, f1.y);
    __nv_bfloat162 h3 = __floats2bfloat162_rn(f1.z, f1.w);
    float2 g0 = __bfloat1622float2(h0), g1 = __bfloat1622float2(h1);
    float2 g2 = __bfloat1622float2(h2), g3 = __bfloat1622float2(h3);
    __nv_bfloat162 l0 = __floats2bfloat162_rn(f0.x - g0.x, f0.y - g0.y);
    __nv_bfloat162 l1 = __floats2bfloat162_rn(f0.z - g1.x, f0.w - g1.y);
    __nv_bfloat162 l2 = __floats2bfloat162_rn(f1.x - g2.x, f1.y - g2.y);
    __nv_bfloat162 l3 = __floats2bfloat162_rn(f1.z - g3.x, f1.w - g3.y);
    *(uint4*)hip = make_uint4(bits(h0), bits(h1), bits(h2), bits(h3));
    *(uint4*)lop = make_uint4(bits(l0), bits(l1), bits(l2), bits(l3));
}

// ---------------------------------------------------------------------------
// HMMA split-bf16 GEMM body: C[M,N] = A[M,K] @ W[N,K]^T + bias (fp32 in/out)
// ---------------------------------------------------------------------------
__device__ __forceinline__ void hmma_gemm_body(
    const float* __restrict__ A, const float* __restrict__ W,
    const float* __restrict__ bias, float* __restrict__ C)
{
    extern __shared__ char sm[];
    const int tid  = threadIdx.x;
    const int lane = tid & 31;
    const int wid  = tid >> 5;
    const int wm   = wid & 1;        // warp m: 0/1 -> 64 rows
    const int wn   = wid >> 1;       // warp n: 0..3 -> 32 cols
    const int m0   = blockIdx.y * 128;
    const int n0   = blockIdx.x * 128;
    const uint32_t sb = smem_u32(sm);

    float d[4][4][4];
#pragma unroll
    for (int mt = 0; mt < 4; mt++)
#pragma unroll
        for (int nt = 0; nt < 4; nt++)
#pragma unroll
            for (int e = 0; e < 4; e++) d[mt][nt][e] = 0.f;

    // ldmatrix per-lane address offsets (bytes), row stride RSB=80 conflict-free
    const int a_lane = (lane & 15) * RSB + (lane >> 4) * 16;
    const int b_lane = ((lane & 7) + ((lane >> 4) << 3)) * RSB + ((lane >> 3) & 1) * 16;

    // global loader mapping: 512 (row, k8-unit) cells per operand, 2 per thread
    int rrow[2], ru[2];
#pragma unroll
    for (int i = 0; i < 2; i++) { int u = tid + i * 256; rrow[i] = u >> 2; ru[i] = u & 3; }

    float4 ra[2][2], rw[2][2];

    auto LDG = [&](int c) {
        const int k0 = c * KC;
#pragma unroll
        for (int i = 0; i < 2; i++) {
            const float* ap = A + (size_t)(m0 + rrow[i]) * D_MODEL + k0 + ru[i] * 8;
            ra[i][0] = *(const float4*)(ap);
            ra[i][1] = *(const float4*)(ap + 4);
            const float* wp = W + (size_t)(n0 + rrow[i]) * D_MODEL + k0 + ru[i] * 8;
            rw[i][0] = *(const float4*)(wp);
            rw[i][1] = *(const float4*)(wp + 4);
        }
    };
    auto STORE = [&](int stg) {
        char* base = sm + stg * STAGEB;
#pragma unroll
        for (int i = 0; i < 2; i++) {
            const int off = rrow[i] * RSB + ru[i] * 16;
            cvt_store(base + off,           base + OPB  + off, ra[i][0], ra[i][1]);   // A hi/lo
            cvt_store(base + 2*OPB + off,   base + 3*OPB + off, rw[i][0], rw[i][1]);  // W hi/lo
        }
    };

    auto LD_A = [&](uint32_t abase, int t, uint32_t af[4][4]) {
#pragma unroll
        for (int mt = 0; mt < 4; mt++)
            ldsm4(af[mt], abase + (wm*64 + mt*16) * RSB + t*32 + a_lane);
    };
    auto LD_B = [&](uint32_t wbase, int t, uint32_t bf[4][2]) {
#pragma unroll
        for (int nh = 0; nh < 2; nh++) {
            uint32_t r[4];
            ldsm4(r, wbase + (wn*32 + nh*16) * RSB + t*32 + b_lane);
            bf[nh*2+0][0] = r[0]; bf[nh*2+0][1] = r[1];
            bf[nh*2+1][0] = r[2]; bf[nh*2+1][1] = r[3];
        }
    };
    auto MMA16 = [&](const uint32_t af[4][4], const uint32_t bf[4][2]) {
#pragma unroll
        for (int mt = 0; mt < 4; mt++)
#pragma unroll
            for (int nt = 0; nt < 4; nt++)
                mma_bf16(d[mt][nt], af[mt], bf[nt]);
    };

    auto MMA_CHUNK = [&](int stg) {
        const uint32_t base = sb + stg * STAGEB;
        uint32_t af[4][4], bf[4][2];
#pragma unroll
        for (int t = 0; t < 2; t++) {
            LD_A(base, t, af);            // A hi
            LD_B(base + 2*OPB, t, bf);    // W hi
            MMA16(af, bf);                // hh
            LD_B(base + 3*OPB, t, bf);    // W lo
            MMA16(af, bf);                // hl
            LD_A(base + OPB, t, af);      // A lo
            LD_B(base + 2*OPB, t, bf);    // W hi
            MMA16(af, bf);                // lh
        }
    };

    // pipeline: reg-prefetch globals for c+1 while MMA on c; ping-pong smem
    LDG(0);
    STORE(0);
    __syncthreads();
    for (int c = 0; c < NCHUNK; c++) {
        if (c + 1 < NCHUNK) LDG(c + 1);
        MMA_CHUNK(c & 1);
        __syncthreads();
        if (c + 1 < NCHUNK) { STORE((c + 1) & 1); __syncthreads(); }
    }

    // epilogue: add bias, write fp32
    const int g = lane >> 2, tq = lane & 3;
#pragma unroll
    for (int mt = 0; mt < 4; mt++) {
#pragma unroll
        for (int nt = 0; nt < 4; nt++) {
            const int row = m0 + wm*64 + mt*16 + g;
            const int col = n0 + wn*32 + nt*8 + tq*2;
            const float b0 = bias[col], b1 = bias[col + 1];
            float2 v0 = make_float2(d[mt][nt][0] + b0, d[mt][nt][1] + b1);
            float2 v1 = make_float2(d[mt][nt][2] + b0, d[mt][nt][3] + b1);
            *(float2*)&C[(size_t)row * D_MODEL + col]       = v0;
            *(float2*)&C[(size_t)(row + 8) * D_MODEL + col] = v1;
        }
    }
}

__global__ __launch_bounds__(256, 1) void tc_qkv_kernel(
    const float* __restrict__ q, const float* __restrict__ k, const float* __restrict__ v,
    const float* __restrict__ Wq, const float* __restrict__ bq,
    const float* __restrict__ Wk, const float* __restrict__ bk,
    const float* __restrict__ Wv, const float* __restrict__ bv)
{
    const float *A, *W, *b; float* C;
    if (blockIdx.z == 0)      { A = q; W = Wq; b = bq; C = g_Q; }
    else if (blockIdx.z == 1) { A = k; W = Wk; b = bk; C = g_K; }
    else                      { A = v; W = Wv; b = bv; C = g_V; }
    hmma_gemm_body(A, W, b, C);
}

__global__ __launch_bounds__(256, 1) void tc_out_kernel(
    const float* __restrict__ Wo, const float* __restrict__ bo, float* __restrict__ out)
{
    hmma_gemm_body(g_A, Wo, bo, out);
}

// ---------------------------------------------------------------------------
// Per-query-token score scale (softmax shift invariance kills additive terms)
// ---------------------------------------------------------------------------
__global__ void scale_kernel(const float* __restrict__ phi)
{
    int i = blockIdx.x * 256 + threadIdx.x;
    if (i < MTOT) {
        const float* p = phi + (size_t)i * 8;
        float s = 0.f;
#pragma unroll
        for (int f = 0; f < 8; f++) s += p[f];
        float ph = s * 0.125f;
        g_scl[i] = 1.0f / (8.0f * fmaxf(ph, 1e-6f));
    }
}

// ---------------------------------------------------------------------------
// Flash attention, fp32 SIMT (unchanged — known good)
// ---------------------------------------------------------------------------
__global__ __launch_bounds__(256, 2) void attn_kernel()
{
    extern __shared__ float smf[];
    float* Qs = smf;
    float* Ks = Qs + 64*AP;
    float* Vs = Ks + 64*AP;
    float* Ps = Vs + 64*AP;

    const int b  = blockIdx.z, h = blockIdx.y;
    const int q0 = blockIdx.x * 64;
    const int tid = threadIdx.x;
    const int lr  = tid & 63;
    const int qtr = tid >> 6;
    const int ty  = tid >> 4;
    const int tx  = tid & 15;

    const size_t hoff = (size_t)h * HD;

    {
        const float* Qg = g_Q + ((size_t)(b*TT + q0 + lr)) * D_MODEL + hoff + qtr*16;
#pragma unroll
        for (int u = 0; u < 4; u++) {
            float4 v = *(const float4*)(Qg + u*4);
            int c = qtr*16 + u*4;
            Qs[(c+0)*AP + lr] = v.x; Qs[(c+1)*AP + lr] = v.y;
            Qs[(c+2)*AP + lr] = v.z; Qs[(c+3)*AP + lr] = v.w;
        }
    }

    float rs[4], m[4], l[4], o[4][4];
#pragma unroll
    for (int i = 0; i < 4; i++) {
        rs[i] = g_scl[b*TT + q0 + ty*4 + i];
        m[i] = -1e30f; l[i] = 0.f;
#pragma unroll
        for (int j = 0; j < 4; j++) o[i][j] = 0.f;
    }

    for (int kt = 0; kt < TT/64; kt++) {
        __syncthreads();
        const int k0 = kt * 64;
        {
            const float* Kg = g_K + ((size_t)(b*TT + k0 + lr)) * D_MODEL + hoff + qtr*16;
            const float* Vg = g_V + ((size_t)(b*TT + k0 + lr)) * D_MODEL + hoff + qtr*16;
#pragma unroll
            for (int u = 0; u < 4; u++) {
                int c = qtr*16 + u*4;
                float4 kv = *(const float4*)(Kg + u*4);
                Ks[(c+0)*AP + lr] = kv.x; Ks[(c+1)*AP + lr] = kv.y;
                Ks[(c+2)*AP + lr] = kv.z; Ks[(c+3)*AP + lr] = kv.w;
                float4 vv = *(const float4*)(Vg + u*4);
                *(float4*)&Vs[lr*AP + c] = vv;
            }
        }
        __syncthreads();

        float s[4][4];
#pragma unroll
        for (int i = 0; i < 4; i++)
#pragma unroll
            for (int j = 0; j < 4; j++) s[i][j] = 0.f;

#pragma unroll 16
        for (int kk = 0; kk < 64; kk++) {
            float4 qv = *(const float4*)&Qs[kk*AP + ty*4];
            float4 kv = *(const float4*)&Ks[kk*AP + tx*4];
            s[0][0] += qv.x*kv.x; s[0][1] += qv.x*kv.y; s[0][2] += qv.x*kv.z; s[0][3] += qv.x*kv.w;
            s[1][0] += qv.y*kv.x; s[1][1] += qv.y*kv.y; s[1][2] += qv.y*kv.z; s[1][3] += qv.y*kv.w;
            s[2][0] += qv.z*kv.x; s[2][1] += qv.z*kv.y; s[2][2] += qv.z*kv.z; s[2][3] += qv.z*kv.w;
            s[3][0] += qv.w*kv.x; s[3][1] += qv.w*kv.y; s[3][2] += qv.w*kv.z; s[3][3] += qv.w*kv.w;
        }

#pragma unroll
        for (int i = 0; i < 4; i++) {
#pragma unroll
            for (int j = 0; j < 4; j++) s[i][j] *= rs[i];
            float tm = fmaxf(fmaxf(s[i][0], s[i][1]), fmaxf(s[i][2], s[i][3]));
#pragma unroll
            for (int off = 8; off >= 1; off >>= 1)
                tm = fmaxf(tm, __shfl_xor_sync(0xffffffffu, tm, off));
            float mn = fmaxf(m[i], tm);
            float corr = __expf(m[i] - mn);
            m[i] = mn;
            float ts = 0.f;
#pragma unroll
            for (int j = 0; j < 4; j++) { s[i][j] = __expf(s[i][j] - mn); ts += s[i][j]; }
#pragma unroll
            for (int off = 8; off >= 1; off >>= 1)
                ts += __shfl_xor_sync(0xffffffffu, ts, off);
            l[i] = l[i]*corr + ts;
#pragma unroll
            for (int j = 0; j < 4; j++) o[i][j] *= corr;
            *(float4*)&Ps[(ty*4+i)*AP + tx*4] = make_float4(s[i][0], s[i][1], s[i][2], s[i][3]);
        }
        __syncthreads();

#pragma unroll 16
        for (int kk = 0; kk < 64; kk++) {
            float4 vv = *(const float4*)&Vs[kk*AP + tx*4];
            float p0 = Ps[(ty*4+0)*AP + kk];
            float p1 = Ps[(ty*4+1)*AP + kk];
            float p2 = Ps[(ty*4+2)*AP + kk];
            float p3 = Ps[(ty*4+3)*AP + kk];
            o[0][0] += p0*vv.x; o[0][1] += p0*vv.y; o[0][2] += p0*vv.z; o[0][3] += p0*vv.w;
            o[1][0] += p1*vv.x; o[1][1] += p1*vv.y; o[1][2] += p1*vv.z; o[1][3] += p1*vv.w;
            o[2][0] += p2*vv.x; o[2][1] += p2*vv.y; o[2][2] += p2*vv.z; o[2][3] += p2*vv.w;
            o[3][0] += p3*vv.x; o[3][1] += p3*vv.y; o[3][2] += p3*vv.z; o[3][3] += p3*vv.w;
        }
    }

#pragma unroll
    for (int i = 0; i < 4; i++) {
        float inv = 1.0f / l[i];
        float* op = g_A + ((size_t)(b*TT + q0 + ty*4 + i)) * D_MODEL + hoff + tx*4;
        *(float4*)op = make_float4(o[i][0]*inv, o[i][1]*inv, o[i][2]*inv, o[i][3]*inv);
    }
}

// ---------------------------------------------------------------------------
extern "C" void kernel_launch(void* const* d_in, const int* in_sizes, int n_in,
                              void* d_out, int out_size)
{
    const float* query = (const float*)d_in[0];
    const float* key   = (const float*)d_in[1];
    const float* value = (const float*)d_in[2];
    const float* phi   = (const float*)d_in[3];
    // d_in[4] logvar, d_in[13] w_sigma, d_in[14] w_phi: cancel under softmax
    const float* Wq = (const float*)d_in[5];
    const float* bq = (const float*)d_in[6];
    const float* Wk = (const float*)d_in[7];
    const float* bk = (const float*)d_in[8];
    const float* Wv = (const float*)d_in[9];
    const float* bv = (const float*)d_in[10];
    const float* Wo = (const float*)d_in[11];
    const float* bo = (const float*)d_in[12];
    float* out = (float*)d_out;

    cudaFuncSetAttribute(tc_qkv_kernel, cudaFuncAttributeMaxDynamicSharedMemorySize, GEMM_SMEM);
    cudaFuncSetAttribute(tc_out_kernel, cudaFuncAttributeMaxDynamicSharedMemorySize, GEMM_SMEM);
    cudaFuncSetAttribute(attn_kernel,   cudaFuncAttributeMaxDynamicSharedMemorySize, ATTN_SMEM);

    tc_qkv_kernel<<<dim3(D_MODEL/128, MTOT/128, 3), 256, GEMM_SMEM>>>(
        query, key, value, Wq, bq, Wk, bk, Wv, bv);
    scale_kernel<<<(MTOT + 255)/256, 256>>>(phi);
    attn_kernel<<<dim3(TT/64, HEADS, BB), 256, ATTN_SMEM>>>();
    tc_out_kernel<<<dim3(D_MODEL/128, MTOT/128, 1), 256, GEMM_SMEM>>>(Wo, bo, out);
}

// round 5
// speedup vs baseline: 2.6724x; 1.9347x over previous
#include <cuda_runtime.h>
#include <cuda_bf16.h>
#include <cstdint>

#define D_MODEL 1024
#define HEADS   16
#define HD      64
#define BB      2
#define TT      2048
#define MTOT    (BB*TT)

// ---------------- HMMA (mma.sync) GEMM config (unchanged from R4) -------
#define KC      32
#define NCHUNK  (D_MODEL/KC)       // 32
#define RSB     80                 // smem row stride bytes (32 bf16 + 16B pad)
#define OPB     (128*RSB)
#define STAGEB  (4*OPB)
#define GEMM_SMEM (2*STAGEB)

// ---------------- HMMA attention config ----------------
#define ARS     144                // row stride bytes for 64-bf16 rows (128+16 pad)
#define QTILE   (128*ARS)          // 18432 B
#define KTILE   (64*ARS)           // 9216 B
#define STG     (4*KTILE)          // Khi,Klo,Vthi,Vtlo = 36864 B
#define ATTN_SMEM (2*QTILE + 2*STG)  // 110592 B
#define NKT     (TT/64)            // 32 key tiles

// Scratch (device globals: allocations forbidden)
__device__ float g_Q[(size_t)MTOT * D_MODEL];
__device__ float g_K[(size_t)MTOT * D_MODEL];
__device__ float g_V[(size_t)MTOT * D_MODEL];
__device__ float g_A[(size_t)MTOT * D_MODEL];
__device__ float g_scl[MTOT];

// ---------------- helpers ----------------
__device__ __forceinline__ uint32_t smem_u32(const void* p) {
    uint32_t a;
    asm("{ .reg .u64 t; cvta.to.shared.u64 t, %1; cvt.u32.u64 %0, t; }" : "=r"(a) : "l"(p));
    return a;
}
__device__ __forceinline__ void ldsm4(uint32_t* r, uint32_t addr) {
    asm volatile("ldmatrix.sync.aligned.m8n8.x4.shared.b16 {%0,%1,%2,%3}, [%4];"
                 : "=r"(r[0]), "=r"(r[1]), "=r"(r[2]), "=r"(r[3]) : "r"(addr));
}
__device__ __forceinline__ void mma_bf16(float* d, const uint32_t* a, const uint32_t* b) {
    asm volatile("mma.sync.aligned.m16n8k16.row.col.f32.bf16.bf16.f32 "
                 "{%0,%1,%2,%3}, {%4,%5,%6,%7}, {%8,%9}, {%0,%1,%2,%3};"
                 : "+f"(d[0]), "+f"(d[1]), "+f"(d[2]), "+f"(d[3])
                 : "r"(a[0]), "r"(a[1]), "r"(a[2]), "r"(a[3]), "r"(b[0]), "r"(b[1]));
}
__device__ __forceinline__ uint32_t bits(const __nv_bfloat162& h) {
    return *reinterpret_cast<const uint32_t*>(&h);
}
// 8 fp32 -> 8 bf16 hi (16B) + 8 bf16 lo (16B)
__device__ __forceinline__ void cvt_store(char* hip, char* lop,
                                          const float4& f0, const float4& f1) {
    __nv_bfloat162 h0 = __floats2bfloat162_rn(f0.x, f0.y);
    __nv_bfloat162 h1 = __floats2bfloat162_rn(f0.z, f0.w);
    __nv_bfloat162 h2 = __floats2bfloat162_rn(f1.x, f1.y);
    __nv_bfloat162 h3 = __floats2bfloat162_rn(f1.z, f1.w);
    float2 g0 = __bfloat1622float2(h0), g1 = __bfloat1622float2(h1);
    float2 g2 = __bfloat1622float2(h2), g3 = __bfloat1622float2(h3);
    __nv_bfloat162 l0 = __floats2bfloat162_rn(f0.x - g0.x, f0.y - g0.y);
    __nv_bfloat162 l1 = __floats2bfloat162_rn(f0.z - g1.x, f0.w - g1.y);
    __nv_bfloat162 l2 = __floats2bfloat162_rn(f1.x - g2.x, f1.y - g2.y);
    __nv_bfloat162 l3 = __floats2bfloat162_rn(f1.z - g3.x, f1.w - g3.y);
    *(uint4*)hip = make_uint4(bits(h0), bits(h1), bits(h2), bits(h3));
    *(uint4*)lop = make_uint4(bits(l0), bits(l1), bits(l2), bits(l3));
}
// pack 2 fp32 -> (hi bf16x2, lo bf16x2)
__device__ __forceinline__ void mk_hilo(uint32_t& hi, uint32_t& lo, float x, float y) {
    __nv_bfloat162 h = __floats2bfloat162_rn(x, y);
    float2 f = __bfloat1622float2(h);
    __nv_bfloat162 l = __floats2bfloat162_rn(x - f.x, y - f.y);
    hi = bits(h); lo = bits(l);
}

// ---------------------------------------------------------------------------
// HMMA split-bf16 GEMM body (unchanged from R4 — verified)
// ---------------------------------------------------------------------------
__device__ __forceinline__ void hmma_gemm_body(
    const float* __restrict__ A, const float* __restrict__ W,
    const float* __restrict__ bias, float* __restrict__ C)
{
    extern __shared__ char sm[];
    const int tid  = threadIdx.x;
    const int lane = tid & 31;
    const int wid  = tid >> 5;
    const int wm   = wid & 1;
    const int wn   = wid >> 1;
    const int m0   = blockIdx.y * 128;
    const int n0   = blockIdx.x * 128;
    const uint32_t sb = smem_u32(sm);

    float d[4][4][4];
#pragma unroll
    for (int mt = 0; mt < 4; mt++)
#pragma unroll
        for (int nt = 0; nt < 4; nt++)
#pragma unroll
            for (int e = 0; e < 4; e++) d[mt][nt][e] = 0.f;

    const int a_lane = (lane & 15) * RSB + (lane >> 4) * 16;
    const int b_lane = ((lane & 7) + ((lane >> 4) << 3)) * RSB + ((lane >> 3) & 1) * 16;

    int rrow[2], ru[2];
#pragma unroll
    for (int i = 0; i < 2; i++) { int u = tid + i * 256; rrow[i] = u >> 2; ru[i] = u & 3; }

    float4 ra[2][2], rw[2][2];

    auto LDG = [&](int c) {
        const int k0 = c * KC;
#pragma unroll
        for (int i = 0; i < 2; i++) {
            const float* ap = A + (size_t)(m0 + rrow[i]) * D_MODEL + k0 + ru[i] * 8;
            ra[i][0] = *(const float4*)(ap);
            ra[i][1] = *(const float4*)(ap + 4);
            const float* wp = W + (size_t)(n0 + rrow[i]) * D_MODEL + k0 + ru[i] * 8;
            rw[i][0] = *(const float4*)(wp);
            rw[i][1] = *(const float4*)(wp + 4);
        }
    };
    auto STORE = [&](int stg) {
        char* base = sm + stg * STAGEB;
#pragma unroll
        for (int i = 0; i < 2; i++) {
            const int off = rrow[i] * RSB + ru[i] * 16;
            cvt_store(base + off,           base + OPB  + off, ra[i][0], ra[i][1]);
            cvt_store(base + 2*OPB + off,   base + 3*OPB + off, rw[i][0], rw[i][1]);
        }
    };

    auto LD_A = [&](uint32_t abase, int t, uint32_t af[4][4]) {
#pragma unroll
        for (int mt = 0; mt < 4; mt++)
            ldsm4(af[mt], abase + (wm*64 + mt*16) * RSB + t*32 + a_lane);
    };
    auto LD_B = [&](uint32_t wbase, int t, uint32_t bf[4][2]) {
#pragma unroll
        for (int nh = 0; nh < 2; nh++) {
            uint32_t r[4];
            ldsm4(r, wbase + (wn*32 + nh*16) * RSB + t*32 + b_lane);
            bf[nh*2+0][0] = r[0]; bf[nh*2+0][1] = r[1];
            bf[nh*2+1][0] = r[2]; bf[nh*2+1][1] = r[3];
        }
    };
    auto MMA16 = [&](const uint32_t af[4][4], const uint32_t bf[4][2]) {
#pragma unroll
        for (int mt = 0; mt < 4; mt++)
#pragma unroll
            for (int nt = 0; nt < 4; nt++)
                mma_bf16(d[mt][nt], af[mt], bf[nt]);
    };

    auto MMA_CHUNK = [&](int stg) {
        const uint32_t base = sb + stg * STAGEB;
        uint32_t af[4][4], bf[4][2];
#pragma unroll
        for (int t = 0; t < 2; t++) {
            LD_A(base, t, af);
            LD_B(base + 2*OPB, t, bf);
            MMA16(af, bf);
            LD_B(base + 3*OPB, t, bf);
            MMA16(af, bf);
            LD_A(base + OPB, t, af);
            LD_B(base + 2*OPB, t, bf);
            MMA16(af, bf);
        }
    };

    LDG(0);
    STORE(0);
    __syncthreads();
    for (int c = 0; c < NCHUNK; c++) {
        if (c + 1 < NCHUNK) LDG(c + 1);
        MMA_CHUNK(c & 1);
        __syncthreads();
        if (c + 1 < NCHUNK) { STORE((c + 1) & 1); __syncthreads(); }
    }

    const int g = lane >> 2, tq = lane & 3;
#pragma unroll
    for (int mt = 0; mt < 4; mt++) {
#pragma unroll
        for (int nt = 0; nt < 4; nt++) {
            const int row = m0 + wm*64 + mt*16 + g;
            const int col = n0 + wn*32 + nt*8 + tq*2;
            const float b0 = bias[col], b1 = bias[col + 1];
            float2 v0 = make_float2(d[mt][nt][0] + b0, d[mt][nt][1] + b1);
            float2 v1 = make_float2(d[mt][nt][2] + b0, d[mt][nt][3] + b1);
            *(float2*)&C[(size_t)row * D_MODEL + col]       = v0;
            *(float2*)&C[(size_t)(row + 8) * D_MODEL + col] = v1;
        }
    }
}

__global__ __launch_bounds__(256, 1) void tc_qkv_kernel(
    const float* __restrict__ q, const float* __restrict__ k, const float* __restrict__ v,
    const float* __restrict__ Wq, const float* __restrict__ bq,
    const float* __restrict__ Wk, const float* __restrict__ bk,
    const float* __restrict__ Wv, const float* __restrict__ bv)
{
    const float *A, *W, *b; float* C;
    if (blockIdx.z == 0)      { A = q; W = Wq; b = bq; C = g_Q; }
    else if (blockIdx.z == 1) { A = k; W = Wk; b = bk; C = g_K; }
    else                      { A = v; W = Wv; b = bv; C = g_V; }
    hmma_gemm_body(A, W, b, C);
}

__global__ __launch_bounds__(256, 1) void tc_out_kernel(
    const float* __restrict__ Wo, const float* __restrict__ bo, float* __restrict__ out)
{
    hmma_gemm_body(g_A, Wo, bo, out);
}

// ---------------------------------------------------------------------------
// Per-query-token score scale
// ---------------------------------------------------------------------------
__global__ void scale_kernel(const float* __restrict__ phi)
{
    int i = blockIdx.x * 256 + threadIdx.x;
    if (i < MTOT) {
        const float* p = phi + (size_t)i * 8;
        float s = 0.f;
#pragma unroll
        for (int f = 0; f < 8; f++) s += p[f];
        float ph = s * 0.125f;
        g_scl[i] = 1.0f / (8.0f * fmaxf(ph, 1e-6f));
    }
}

// ---------------------------------------------------------------------------
// HMMA flash attention (split-bf16). CTA = (128 queries, head h, batch b).
// 8 warps x 16 query rows. S = QK^T (3-MMA split), online softmax in frags,
// O += P V (3-MMA split, V transposed into smem at load).
// ---------------------------------------------------------------------------
__global__ __launch_bounds__(256, 1) void attn_mma_kernel()
{
    extern __shared__ char sm[];
    const int tid  = threadIdx.x;
    const int lane = tid & 31;
    const int wid  = tid >> 5;
    const int b    = blockIdx.z, h = blockIdx.y;
    const int q0   = blockIdx.x * 128;
    const uint32_t sb = smem_u32(sm);
    const size_t hoff = (size_t)h * HD;

    const int a_lane = (lane & 15) * ARS + (lane >> 4) * 16;
    const int b_lane = ((lane & 7) + ((lane >> 4) << 3)) * ARS + ((lane >> 3) & 1) * 16;

    // ---- load Q tile (128x64 fp32) -> Qhi/Qlo smem ----
#pragma unroll
    for (int i = 0; i < 4; i++) {
        int u = tid + i * 256;          // 0..1023 cells of 8 floats
        int row = u >> 3, un = u & 7;
        const float* qp = g_Q + (size_t)(b*TT + q0 + row) * D_MODEL + hoff + un * 8;
        float4 f0 = *(const float4*)qp;
        float4 f1 = *(const float4*)(qp + 4);
        cvt_store(sm + row*ARS + un*16, sm + QTILE + row*ARS + un*16, f0, f1);
    }
    __syncthreads();

    // ---- Q fragments to registers (rows wid*16 .. +16) ----
    uint32_t qh[4][4], ql[4][4];
#pragma unroll
    for (int kc = 0; kc < 4; kc++) {
        ldsm4(qh[kc], sb         + (wid*16)*ARS + kc*32 + a_lane);
        ldsm4(ql[kc], sb + QTILE + (wid*16)*ARS + kc*32 + a_lane);
    }

    // per-thread row scales / softmax state (rows g and g+8 of warp tile)
    const int g = lane >> 2;
    const float rs0 = g_scl[b*TT + q0 + wid*16 + g];
    const float rs1 = g_scl[b*TT + q0 + wid*16 + g + 8];
    float m0 = -1e30f, m1 = -1e30f, l0 = 0.f, l1 = 0.f;
    float o[8][4];
#pragma unroll
    for (int dn = 0; dn < 8; dn++)
#pragma unroll
        for (int e = 0; e < 4; e++) o[dn][e] = 0.f;

    // KV loader mapping: row = key (0..63), 16 consecutive dims per thread
    const int krow = tid >> 2;
    const int kc0f = (tid & 3) * 16;
    float4 kf[4], vf[4];

    auto LDGKV = [&](int c) {
        const float* kp = g_K + (size_t)(b*TT + c*64 + krow) * D_MODEL + hoff + kc0f;
        const float* vp = g_V + (size_t)(b*TT + c*64 + krow) * D_MODEL + hoff + kc0f;
#pragma unroll
        for (int j = 0; j < 4; j++) { kf[j] = *(const float4*)(kp + j*4); vf[j] = *(const float4*)(vp + j*4); }
    };
    auto STOREKV = [&](int stg) {
        char* base = sm + 2*QTILE + stg*STG;           // Khi
        char* klo  = base + KTILE;
        char* vthi = base + 2*KTILE;                   // Vt[dim][key]
        char* vtlo = base + 3*KTILE;
        // K: row-major hi/lo
        cvt_store(base + krow*ARS + kc0f*2,      klo + krow*ARS + kc0f*2,      kf[0], kf[1]);
        cvt_store(base + krow*ARS + kc0f*2 + 16, klo + krow*ARS + kc0f*2 + 16, kf[2], kf[3]);
        // V: transpose scalar stores Vt[dim][key]
#pragma unroll
        for (int j = 0; j < 4; j++) {
            const float x[4] = { vf[j].x, vf[j].y, vf[j].z, vf[j].w };
#pragma unroll
            for (int e = 0; e < 4; e++) {
                int d = kc0f + j*4 + e;
                __nv_bfloat16 hi = __float2bfloat16_rn(x[e]);
                __nv_bfloat16 lo = __float2bfloat16_rn(x[e] - __bfloat162float(hi));
                *(__nv_bfloat16*)(vthi + d*ARS + krow*2) = hi;
                *(__nv_bfloat16*)(vtlo + d*ARS + krow*2) = lo;
            }
        }
    };

    auto COMPUTE = [&](int stg) {
        const uint32_t kh = sb + 2*QTILE + stg*STG;
        const uint32_t kl = kh + KTILE;
        const uint32_t vh = kh + 2*KTILE;
        const uint32_t vl = kh + 3*KTILE;

        // ---- S = Q K^T (3-MMA split), s[nt] = keys [nt*8, nt*8+8) ----
        float s[8][4];
#pragma unroll
        for (int nt = 0; nt < 8; nt++)
#pragma unroll
            for (int e = 0; e < 4; e++) s[nt][e] = 0.f;

#pragma unroll
        for (int kc = 0; kc < 4; kc++) {
#pragma unroll
            for (int nq = 0; nq < 4; nq++) {
                uint32_t r[4];
                ldsm4(r, kh + (nq*16)*ARS + kc*32 + b_lane);
                uint32_t b0[2] = { r[0], r[1] }, b1[2] = { r[2], r[3] };
                mma_bf16(s[2*nq],   qh[kc], b0);
                mma_bf16(s[2*nq+1], qh[kc], b1);
                mma_bf16(s[2*nq],   ql[kc], b0);
                mma_bf16(s[2*nq+1], ql[kc], b1);
                ldsm4(r, kl + (nq*16)*ARS + kc*32 + b_lane);
                uint32_t c0[2] = { r[0], r[1] }, c1[2] = { r[2], r[3] };
                mma_bf16(s[2*nq],   qh[kc], c0);
                mma_bf16(s[2*nq+1], qh[kc], c1);
            }
        }

        // ---- online softmax on fragments (rows g, g+8; 4 lanes per row) ----
        float tm0 = -1e30f, tm1 = -1e30f;
#pragma unroll
        for (int nt = 0; nt < 8; nt++) {
            s[nt][0] *= rs0; s[nt][1] *= rs0; s[nt][2] *= rs1; s[nt][3] *= rs1;
            tm0 = fmaxf(tm0, fmaxf(s[nt][0], s[nt][1]));
            tm1 = fmaxf(tm1, fmaxf(s[nt][2], s[nt][3]));
        }
        tm0 = fmaxf(tm0, __shfl_xor_sync(0xffffffffu, tm0, 1));
        tm0 = fmaxf(tm0, __shfl_xor_sync(0xffffffffu, tm0, 2));
        tm1 = fmaxf(tm1, __shfl_xor_sync(0xffffffffu, tm1, 1));
        tm1 = fmaxf(tm1, __shfl_xor_sync(0xffffffffu, tm1, 2));
        const float mn0 = fmaxf(m0, tm0), mn1 = fmaxf(m1, tm1);
        const float cr0 = __expf(m0 - mn0), cr1 = __expf(m1 - mn1);
        m0 = mn0; m1 = mn1;
        float ts0 = 0.f, ts1 = 0.f;
#pragma unroll
        for (int nt = 0; nt < 8; nt++) {
            s[nt][0] = __expf(s[nt][0] - mn0); ts0 += s[nt][0];
            s[nt][1] = __expf(s[nt][1] - mn0); ts0 += s[nt][1];
            s[nt][2] = __expf(s[nt][2] - mn1); ts1 += s[nt][2];
            s[nt][3] = __expf(s[nt][3] - mn1); ts1 += s[nt][3];
        }
        ts0 += __shfl_xor_sync(0xffffffffu, ts0, 1);
        ts0 += __shfl_xor_sync(0xffffffffu, ts0, 2);
        ts1 += __shfl_xor_sync(0xffffffffu, ts1, 1);
        ts1 += __shfl_xor_sync(0xffffffffu, ts1, 2);
        l0 = l0 * cr0 + ts0;
        l1 = l1 * cr1 + ts1;
#pragma unroll
        for (int dn = 0; dn < 8; dn++) {
            o[dn][0] *= cr0; o[dn][1] *= cr0; o[dn][2] *= cr1; o[dn][3] *= cr1;
        }

        // ---- O += P V (3-MMA split); A=P from registers, B=Vt via ldmatrix ----
#pragma unroll
        for (int kc = 0; kc < 4; kc++) {
            uint32_t ah[4], al[4];
            mk_hilo(ah[0], al[0], s[2*kc][0],   s[2*kc][1]);
            mk_hilo(ah[1], al[1], s[2*kc][2],   s[2*kc][3]);
            mk_hilo(ah[2], al[2], s[2*kc+1][0], s[2*kc+1][1]);
            mk_hilo(ah[3], al[3], s[2*kc+1][2], s[2*kc+1][3]);
#pragma unroll
            for (int dq = 0; dq < 4; dq++) {
                uint32_t r[4];
                ldsm4(r, vh + (dq*16)*ARS + kc*32 + b_lane);
                uint32_t b0[2] = { r[0], r[1] }, b1[2] = { r[2], r[3] };
                mma_bf16(o[2*dq],   ah, b0);
                mma_bf16(o[2*dq+1], ah, b1);
                mma_bf16(o[2*dq],   al, b0);
                mma_bf16(o[2*dq+1], al, b1);
                ldsm4(r, vl + (dq*16)*ARS + kc*32 + b_lane);
                uint32_t c0[2] = { r[0], r[1] }, c1[2] = { r[2], r[3] };
                mma_bf16(o[2*dq],   ah, c0);
                mma_bf16(o[2*dq+1], ah, c1);
            }
        }
    };

    // ---- main loop over 32 key tiles (double-buffered smem, reg prefetch) ----
    LDGKV(0);
    STOREKV(0);
    __syncthreads();
    for (int c = 0; c < NKT; c++) {
        if (c + 1 < NKT) LDGKV(c + 1);
        COMPUTE(c & 1);
        if (c + 1 < NKT) STOREKV((c + 1) & 1);
        __syncthreads();
    }

    // ---- normalize & write head output ----
    const float inv0 = 1.0f / l0, inv1 = 1.0f / l1;
    const int t2 = (lane & 3) * 2;
    const size_t row0 = (size_t)(b*TT + q0 + wid*16 + g);
#pragma unroll
    for (int dn = 0; dn < 8; dn++) {
        *(float2*)&g_A[row0 * D_MODEL + hoff + dn*8 + t2] =
            make_float2(o[dn][0]*inv0, o[dn][1]*inv0);
        *(float2*)&g_A[(row0 + 8) * D_MODEL + hoff + dn*8 + t2] =
            make_float2(o[dn][2]*inv1, o[dn][3]*inv1);
    }
}

// ---------------------------------------------------------------------------
extern "C" void kernel_launch(void* const* d_in, const int* in_sizes, int n_in,
                              void* d_out, int out_size)
{
    const float* query = (const float*)d_in[0];
    const float* key   = (const float*)d_in[1];
    const float* value = (const float*)d_in[2];
    const float* phi   = (const float*)d_in[3];
    // d_in[4] logvar, d_in[13] w_sigma, d_in[14] w_phi: cancel under softmax
    const float* Wq = (const float*)d_in[5];
    const float* bq = (const float*)d_in[6];
    const float* Wk = (const float*)d_in[7];
    const float* bk = (const float*)d_in[8];
    const float* Wv = (const float*)d_in[9];
    const float* bv = (const float*)d_in[10];
    const float* Wo = (const float*)d_in[11];
    const float* bo = (const float*)d_in[12];
    float* out = (float*)d_out;

    cudaFuncSetAttribute(tc_qkv_kernel,  cudaFuncAttributeMaxDynamicSharedMemorySize, GEMM_SMEM);
    cudaFuncSetAttribute(tc_out_kernel,  cudaFuncAttributeMaxDynamicSharedMemorySize, GEMM_SMEM);
    cudaFuncSetAttribute(attn_mma_kernel, cudaFuncAttributeMaxDynamicSharedMemorySize, ATTN_SMEM);

    tc_qkv_kernel<<<dim3(D_MODEL/128, MTOT/128, 3), 256, GEMM_SMEM>>>(
        query, key, value, Wq, bq, Wk, bk, Wv, bv);
    scale_kernel<<<(MTOT + 255)/256, 256>>>(phi);
    attn_mma_kernel<<<dim3(TT/128, HEADS, BB), 256, ATTN_SMEM>>>();
    tc_out_kernel<<<dim3(D_MODEL/128, MTOT/128, 1), 256, GEMM_SMEM>>>(Wo, bo, out);
}

// round 7
// speedup vs baseline: 2.7692x; 1.0362x over previous
#include <cuda_runtime.h>
#include <cuda_bf16.h>
#include <cstdint>

#define D_MODEL 1024
#define HEADS   16
#define HD      64
#define BB      2
#define TT      2048
#define MTOT    (BB*TT)

// ---------------- HMMA (mma.sync) GEMM config -------
#define KC      32
#define NCHUNK  (D_MODEL/KC)       // 32
#define RSB     80                 // smem row stride bytes (32 bf16 + 16B pad)
#define OPB     (128*RSB)
#define STAGEB  (4*OPB)
#define GEMM_SMEM (2*STAGEB)

// ---------------- HMMA attention config ----------------
#define ARS     144                // row stride bytes for 64-bf16 rows (128+16 pad)
#define QTILE   (128*ARS)          // 18432 B
#define KTILE   (64*ARS)           // 9216 B
#define STG     (4*KTILE)          // Khi,Klo,Vhi,Vlo = 36864 B
#define ATTN_SMEM (2*QTILE + 2*STG)  // 110592 B
#define NKT     (TT/64)            // 32 key tiles

// Scratch (device globals: allocations forbidden)
__device__ float g_Q[(size_t)MTOT * D_MODEL];
__device__ float g_K[(size_t)MTOT * D_MODEL];
__device__ float g_V[(size_t)MTOT * D_MODEL];
__device__ float g_A[(size_t)MTOT * D_MODEL];
__device__ float g_scl[MTOT];

// ---------------- helpers ----------------
__device__ __forceinline__ uint32_t smem_u32(const void* p) {
    uint32_t a;
    asm("{ .reg .u64 t; cvta.to.shared.u64 t, %1; cvt.u32.u64 %0, t; }" : "=r"(a) : "l"(p));
    return a;
}
__device__ __forceinline__ void ldsm4(uint32_t* r, uint32_t addr) {
    asm volatile("ldmatrix.sync.aligned.m8n8.x4.shared.b16 {%0,%1,%2,%3}, [%4];"
                 : "=r"(r[0]), "=r"(r[1]), "=r"(r[2]), "=r"(r[3]) : "r"(addr));
}
__device__ __forceinline__ void ldsm4t(uint32_t* r, uint32_t addr) {
    asm volatile("ldmatrix.sync.aligned.m8n8.x4.trans.shared.b16 {%0,%1,%2,%3}, [%4];"
                 : "=r"(r[0]), "=r"(r[1]), "=r"(r[2]), "=r"(r[3]) : "r"(addr));
}
__device__ __forceinline__ void mma_bf16(float* d, const uint32_t* a, const uint32_t* b) {
    asm volatile("mma.sync.aligned.m16n8k16.row.col.f32.bf16.bf16.f32 "
                 "{%0,%1,%2,%3}, {%4,%5,%6,%7}, {%8,%9}, {%0,%1,%2,%3};"
                 : "+f"(d[0]), "+f"(d[1]), "+f"(d[2]), "+f"(d[3])
                 : "r"(a[0]), "r"(a[1]), "r"(a[2]), "r"(a[3]), "r"(b[0]), "r"(b[1]));
}
__device__ __forceinline__ uint32_t bits(const __nv_bfloat162& h) {
    return *reinterpret_cast<const uint32_t*>(&h);
}
// 8 fp32 -> 8 bf16 hi (16B) + 8 bf16 lo (16B)
__device__ __forceinline__ void cvt_store(char* hip, char* lop,
                                          const float4& f0, const float4& f1) {
    __nv_bfloat162 h0 = __floats2bfloat162_rn(f0.x, f0.y);
    __nv_bfloat162 h1 = __floats2bfloat162_rn(f0.z, f0.w);
    __nv_bfloat162 h2 = __floats2bfloat162_rn(f1.x, f1.y);
    __nv_bfloat162 h3 = __floats2bfloat162_rn(f1.z, f1.w);
    float2 g0 = __bfloat1622float2(h0), g1 = __bfloat1622float2(h1);
    float2 g2 = __bfloat1622float2(h2), g3 = __bfloat1622float2(h3);
    __nv_bfloat162 l0 = __floats2bfloat162_rn(f0.x - g0.x, f0.y - g0.y);
    __nv_bfloat162 l1 = __floats2bfloat162_rn(f0.z - g1.x, f0.w - g1.y);
    __nv_bfloat162 l2 = __floats2bfloat162_rn(f1.x - g2.x, f1.y - g2.y);
    __nv_bfloat162 l3 = __floats2bfloat162_rn(f1.z - g3.x, f1.w - g3.y);
    *(uint4*)hip = make_uint4(bits(h0), bits(h1), bits(h2), bits(h3));
    *(uint4*)lop = make_uint4(bits(l0), bits(l1), bits(l2), bits(l3));
}
// pack 2 fp32 -> (hi bf16x2, lo bf16x2)
__device__ __forceinline__ void mk_hilo(uint32_t& hi, uint32_t& lo, float x, float y) {
    __nv_bfloat162 h = __floats2bfloat162_rn(x, y);
    float2 f = __bfloat1622float2(h);
    __nv_bfloat162 l = __floats2bfloat162_rn(x - f.x, y - f.y);
    hi = bits(h); lo = bits(l);
}

// ---------------------------------------------------------------------------
// HMMA split-bf16 GEMM body: one __syncthreads per K-chunk; STORE(c+1) writes
// the opposite smem stage from MMA(c) so they share a sync interval.
// ---------------------------------------------------------------------------
__device__ __forceinline__ void hmma_gemm_body(
    const float* __restrict__ A, const float* __restrict__ W,
    const float* __restrict__ bias, float* __restrict__ C)
{
    extern __shared__ char sm[];
    const int tid  = threadIdx.x;
    const int lane = tid & 31;
    const int wid  = tid >> 5;
    const int wm   = wid & 1;
    const int wn   = wid >> 1;
    const int m0   = blockIdx.y * 128;
    const int n0   = blockIdx.x * 128;
    const uint32_t sb = smem_u32(sm);

    float d[4][4][4];
#pragma unroll
    for (int mt = 0; mt < 4; mt++)
#pragma unroll
        for (int nt = 0; nt < 4; nt++)
#pragma unroll
            for (int e = 0; e < 4; e++) d[mt][nt][e] = 0.f;

    const int a_lane = (lane & 15) * RSB + (lane >> 4) * 16;
    const int b_lane = ((lane & 7) + ((lane >> 4) << 3)) * RSB + ((lane >> 3) & 1) * 16;

    int rrow[2], ru[2];
#pragma unroll
    for (int i = 0; i < 2; i++) { int u = tid + i * 256; rrow[i] = u >> 2; ru[i] = u & 3; }

    float4 ra[2][2], rw[2][2];

    auto LDG = [&](int c) {
        const int k0 = c * KC;
#pragma unroll
        for (int i = 0; i < 2; i++) {
            const float* ap = A + (size_t)(m0 + rrow[i]) * D_MODEL + k0 + ru[i] * 8;
            ra[i][0] = *(const float4*)(ap);
            ra[i][1] = *(const float4*)(ap + 4);
            const float* wp = W + (size_t)(n0 + rrow[i]) * D_MODEL + k0 + ru[i] * 8;
            rw[i][0] = *(const float4*)(wp);
            rw[i][1] = *(const float4*)(wp + 4);
        }
    };
    auto STORE = [&](int stg) {
        char* base = sm + stg * STAGEB;
#pragma unroll
        for (int i = 0; i < 2; i++) {
            const int off = rrow[i] * RSB + ru[i] * 16;
            cvt_store(base + off,           base + OPB  + off, ra[i][0], ra[i][1]);
            cvt_store(base + 2*OPB + off,   base + 3*OPB + off, rw[i][0], rw[i][1]);
        }
    };

    auto LD_A = [&](uint32_t abase, int t, uint32_t af[4][4]) {
#pragma unroll
        for (int mt = 0; mt < 4; mt++)
            ldsm4(af[mt], abase + (wm*64 + mt*16) * RSB + t*32 + a_lane);
    };
    auto LD_B = [&](uint32_t wbase, int t, uint32_t bf[4][2]) {
#pragma unroll
        for (int nh = 0; nh < 2; nh++) {
            uint32_t r[4];
            ldsm4(r, wbase + (wn*32 + nh*16) * RSB + t*32 + b_lane);
            bf[nh*2+0][0] = r[0]; bf[nh*2+0][1] = r[1];
            bf[nh*2+1][0] = r[2]; bf[nh*2+1][1] = r[3];
        }
    };
    auto MMA16 = [&](const uint32_t af[4][4], const uint32_t bf[4][2]) {
#pragma unroll
        for (int mt = 0; mt < 4; mt++)
#pragma unroll
            for (int nt = 0; nt < 4; nt++)
                mma_bf16(d[mt][nt], af[mt], bf[nt]);
    };

    auto MMA_CHUNK = [&](int stg) {
        const uint32_t base = sb + stg * STAGEB;
        uint32_t af[4][4], bf[4][2];
#pragma unroll
        for (int t = 0; t < 2; t++) {
            LD_A(base, t, af);
            LD_B(base + 2*OPB, t, bf);
            MMA16(af, bf);
            LD_B(base + 3*OPB, t, bf);
            MMA16(af, bf);
            LD_A(base + OPB, t, af);
            LD_B(base + 2*OPB, t, bf);
            MMA16(af, bf);
        }
    };

    // single-sync pipeline
    LDG(0); STORE(0);
    LDG(1);
    __syncthreads();
    for (int c = 0; c < NCHUNK; c++) {
        MMA_CHUNK(c & 1);
        if (c + 1 < NCHUNK) STORE((c + 1) & 1);   // opposite stage; prev readers done at last sync
        if (c + 2 < NCHUNK) LDG(c + 2);
        __syncthreads();
    }

    const int g = lane >> 2, tq = lane & 3;
#pragma unroll
    for (int mt = 0; mt < 4; mt++) {
#pragma unroll
        for (int nt = 0; nt < 4; nt++) {
            const int row = m0 + wm*64 + mt*16 + g;
            const int col = n0 + wn*32 + nt*8 + tq*2;
            const float b0 = bias[col], b1 = bias[col + 1];
            float2 v0 = make_float2(d[mt][nt][0] + b0, d[mt][nt][1] + b1);
            float2 v1 = make_float2(d[mt][nt][2] + b0, d[mt][nt][3] + b1);
            *(float2*)&C[(size_t)row * D_MODEL + col]       = v0;
            *(float2*)&C[(size_t)(row + 8) * D_MODEL + col] = v1;
        }
    }
}

__global__ __launch_bounds__(256, 1) void tc_qkv_kernel(
    const float* __restrict__ q, const float* __restrict__ k, const float* __restrict__ v,
    const float* __restrict__ Wq, const float* __restrict__ bq,
    const float* __restrict__ Wk, const float* __restrict__ bk,
    const float* __restrict__ Wv, const float* __restrict__ bv)
{
    const float *A, *W, *b; float* C;
    if (blockIdx.z == 0)      { A = q; W = Wq; b = bq; C = g_Q; }
    else if (blockIdx.z == 1) { A = k; W = Wk; b = bk; C = g_K; }
    else                      { A = v; W = Wv; b = bv; C = g_V; }
    hmma_gemm_body(A, W, b, C);
}

__global__ __launch_bounds__(256, 1) void tc_out_kernel(
    const float* __restrict__ Wo, const float* __restrict__ bo, float* __restrict__ out)
{
    hmma_gemm_body(g_A, Wo, bo, out);
}

// ---------------------------------------------------------------------------
// Per-query-token score scale
// ---------------------------------------------------------------------------
__global__ void scale_kernel(const float* __restrict__ phi)
{
    int i = blockIdx.x * 256 + threadIdx.x;
    if (i < MTOT) {
        const float* p = phi + (size_t)i * 8;
        float s = 0.f;
#pragma unroll
        for (int f = 0; f < 8; f++) s += p[f];
        float ph = s * 0.125f;
        g_scl[i] = 1.0f / (8.0f * fmaxf(ph, 1e-6f));
    }
}

// ---------------------------------------------------------------------------
// HMMA flash attention (split-bf16). V stored ROW-MAJOR [key][dim] hi/lo;
// PV B-fragments come from ldmatrix.x4.trans (no scalar transpose stores).
// ---------------------------------------------------------------------------
__global__ __launch_bounds__(256, 1) void attn_mma_kernel()
{
    extern __shared__ char sm[];
    const int tid  = threadIdx.x;
    const int lane = tid & 31;
    const int wid  = tid >> 5;
    const int b    = blockIdx.z, h = blockIdx.y;
    const int q0   = blockIdx.x * 128;
    const uint32_t sb = smem_u32(sm);
    const size_t hoff = (size_t)h * HD;

    const int a_lane  = (lane & 15) * ARS + (lane >> 4) * 16;
    const int b_lane  = ((lane & 7) + ((lane >> 4) << 3)) * ARS + ((lane >> 3) & 1) * 16;
    const int vt_lane = (lane & 15) * ARS + (lane >> 4) * 16;  // trans-B: rows=keys, +16B for dims 8..15

    // ---- load Q tile (128x64 fp32) -> Qhi/Qlo smem ----
#pragma unroll
    for (int i = 0; i < 4; i++) {
        int u = tid + i * 256;
        int row = u >> 3, un = u & 7;
        const float* qp = g_Q + (size_t)(b*TT + q0 + row) * D_MODEL + hoff + un * 8;
        float4 f0 = *(const float4*)qp;
        float4 f1 = *(const float4*)(qp + 4);
        cvt_store(sm + row*ARS + un*16, sm + QTILE + row*ARS + un*16, f0, f1);
    }
    __syncthreads();

    // ---- Q fragments to registers (rows wid*16 .. +16) ----
    uint32_t qh[4][4], ql[4][4];
#pragma unroll
    for (int kc = 0; kc < 4; kc++) {
        ldsm4(qh[kc], sb         + (wid*16)*ARS + kc*32 + a_lane);
        ldsm4(ql[kc], sb + QTILE + (wid*16)*ARS + kc*32 + a_lane);
    }

    const int g = lane >> 2;
    const float rs0 = g_scl[b*TT + q0 + wid*16 + g];
    const float rs1 = g_scl[b*TT + q0 + wid*16 + g + 8];
    float m0 = -1e30f, m1 = -1e30f, l0 = 0.f, l1 = 0.f;
    float o[8][4];
#pragma unroll
    for (int dn = 0; dn < 8; dn++)
#pragma unroll
        for (int e = 0; e < 4; e++) o[dn][e] = 0.f;

    // KV loader mapping: row = key (0..63), 16 consecutive dims per thread
    const int krow = tid >> 2;
    const int kc0f = (tid & 3) * 16;
    float4 kf[4], vf[4];

    auto LDGKV = [&](int c) {
        const float* kp = g_K + (size_t)(b*TT + c*64 + krow) * D_MODEL + hoff + kc0f;
        const float* vp = g_V + (size_t)(b*TT + c*64 + krow) * D_MODEL + hoff + kc0f;
#pragma unroll
        for (int j = 0; j < 4; j++) { kf[j] = *(const float4*)(kp + j*4); vf[j] = *(const float4*)(vp + j*4); }
    };
    auto STOREKV = [&](int stg) {
        char* khi = sm + 2*QTILE + stg*STG;
        char* klo = khi + KTILE;
        char* vhi = khi + 2*KTILE;    // V row-major [key][dim], same layout as K
        char* vlo = khi + 3*KTILE;
        const int off = krow*ARS + kc0f*2;
        cvt_store(khi + off,      klo + off,      kf[0], kf[1]);
        cvt_store(khi + off + 16, klo + off + 16, kf[2], kf[3]);
        cvt_store(vhi + off,      vlo + off,      vf[0], vf[1]);
        cvt_store(vhi + off + 16, vlo + off + 16, vf[2], vf[3]);
    };

    auto COMPUTE = [&](int stg) {
        const uint32_t kh = sb + 2*QTILE + stg*STG;
        const uint32_t kl = kh + KTILE;
        const uint32_t vh = kh + 2*KTILE;
        const uint32_t vl = kh + 3*KTILE;

        // ---- S = Q K^T (3-MMA split) ----
        float s[8][4];
#pragma unroll
        for (int nt = 0; nt < 8; nt++)
#pragma unroll
            for (int e = 0; e < 4; e++) s[nt][e] = 0.f;

#pragma unroll
        for (int kc = 0; kc < 4; kc++) {
#pragma unroll
            for (int nq = 0; nq < 4; nq++) {
                uint32_t r[4];
                ldsm4(r, kh + (nq*16)*ARS + kc*32 + b_lane);
                uint32_t b0[2] = { r[0], r[1] }, b1[2] = { r[2], r[3] };
                mma_bf16(s[2*nq],   qh[kc], b0);
                mma_bf16(s[2*nq+1], qh[kc], b1);
                mma_bf16(s[2*nq],   ql[kc], b0);
                mma_bf16(s[2*nq+1], ql[kc], b1);
                ldsm4(r, kl + (nq*16)*ARS + kc*32 + b_lane);
                uint32_t c0[2] = { r[0], r[1] }, c1[2] = { r[2], r[3] };
                mma_bf16(s[2*nq],   qh[kc], c0);
                mma_bf16(s[2*nq+1], qh[kc], c1);
            }
        }

        // ---- online softmax on fragments ----
        float tm0 = -1e30f, tm1 = -1e30f;
#pragma unroll
        for (int nt = 0; nt < 8; nt++) {
            s[nt][0] *= rs0; s[nt][1] *= rs0; s[nt][2] *= rs1; s[nt][3] *= rs1;
            tm0 = fmaxf(tm0, fmaxf(s[nt][0], s[nt][1]));
            tm1 = fmaxf(tm1, fmaxf(s[nt][2], s[nt][3]));
        }
        tm0 = fmaxf(tm0, __shfl_xor_sync(0xffffffffu, tm0, 1));
        tm0 = fmaxf(tm0, __shfl_xor_sync(0xffffffffu, tm0, 2));
        tm1 = fmaxf(tm1, __shfl_xor_sync(0xffffffffu, tm1, 1));
        tm1 = fmaxf(tm1, __shfl_xor_sync(0xffffffffu, tm1, 2));
        const float mn0 = fmaxf(m0, tm0), mn1 = fmaxf(m1, tm1);
        const float cr0 = __expf(m0 - mn0), cr1 = __expf(m1 - mn1);
        m0 = mn0; m1 = mn1;
        float ts0 = 0.f, ts1 = 0.f;
#pragma unroll
        for (int nt = 0; nt < 8; nt++) {
            s[nt][0] = __expf(s[nt][0] - mn0); ts0 += s[nt][0];
            s[nt][1] = __expf(s[nt][1] - mn0); ts0 += s[nt][1];
            s[nt][2] = __expf(s[nt][2] - mn1); ts1 += s[nt][2];
            s[nt][3] = __expf(s[nt][3] - mn1); ts1 += s[nt][3];
        }
        ts0 += __shfl_xor_sync(0xffffffffu, ts0, 1);
        ts0 += __shfl_xor_sync(0xffffffffu, ts0, 2);
        ts1 += __shfl_xor_sync(0xffffffffu, ts1, 1);
        ts1 += __shfl_xor_sync(0xffffffffu, ts1, 2);
        l0 = l0 * cr0 + ts0;
        l1 = l1 * cr1 + ts1;
#pragma unroll
        for (int dn = 0; dn < 8; dn++) {
            o[dn][0] *= cr0; o[dn][1] *= cr0; o[dn][2] *= cr1; o[dn][3] *= cr1;
        }

        // ---- O += P V (3-MMA split); B-fragments via trans ldmatrix ----
#pragma unroll
        for (int kc = 0; kc < 4; kc++) {
            uint32_t ah[4], al[4];
            mk_hilo(ah[0], al[0], s[2*kc][0],   s[2*kc][1]);
            mk_hilo(ah[1], al[1], s[2*kc][2],   s[2*kc][3]);
            mk_hilo(ah[2], al[2], s[2*kc+1][0], s[2*kc+1][1]);
            mk_hilo(ah[3], al[3], s[2*kc+1][2], s[2*kc+1][3]);
#pragma unroll
            for (int dq = 0; dq < 4; dq++) {
                uint32_t r[4];
                ldsm4t(r, vh + (kc*16)*ARS + dq*32 + vt_lane);
                uint32_t b0[2] = { r[0], r[1] }, b1[2] = { r[2], r[3] };
                mma_bf16(o[2*dq],   ah, b0);
                mma_bf16(o[2*dq+1], ah, b1);
                mma_bf16(o[2*dq],   al, b0);
                mma_bf16(o[2*dq+1], al, b1);
                ldsm4t(r, vl + (kc*16)*ARS + dq*32 + vt_lane);
                uint32_t c0[2] = { r[0], r[1] }, c1[2] = { r[2], r[3] };
                mma_bf16(o[2*dq],   ah, c0);
                mma_bf16(o[2*dq+1], ah, c1);
            }
        }
    };

    // ---- main loop over 32 key tiles ----
    LDGKV(0);
    STOREKV(0);
    __syncthreads();
    for (int c = 0; c < NKT; c++) {
        if (c + 1 < NKT) LDGKV(c + 1);
        COMPUTE(c & 1);
        if (c + 1 < NKT) STOREKV((c + 1) & 1);
        __syncthreads();
    }

    // ---- normalize & write head output ----
    const float inv0 = 1.0f / l0, inv1 = 1.0f / l1;
    const int t2 = (lane & 3) * 2;
    const size_t row0 = (size_t)(b*TT + q0 + wid*16 + g);
#pragma unroll
    for (int dn = 0; dn < 8; dn++) {
        *(float2*)&g_A[row0 * D_MODEL + hoff + dn*8 + t2] =
            make_float2(o[dn][0]*inv0, o[dn][1]*inv0);
        *(float2*)&g_A[(row0 + 8) * D_MODEL + hoff + dn*8 + t2] =
            make_float2(o[dn][2]*inv1, o[dn][3]*inv1);
    }
}

// ---------------------------------------------------------------------------
extern "C" void kernel_launch(void* const* d_in, const int* in_sizes, int n_in,
                              void* d_out, int out_size)
{
    const float* query = (const float*)d_in[0];
    const float* key   = (const float*)d_in[1];
    const float* value = (const float*)d_in[2];
    const float* phi   = (const float*)d_in[3];
    // d_in[4] logvar, d_in[13] w_sigma, d_in[14] w_phi: cancel under softmax
    const float* Wq = (const float*)d_in[5];
    const float* bq = (const float*)d_in[6];
    const float* Wk = (const float*)d_in[7];
    const float* bk = (const float*)d_in[8];
    const float* Wv = (const float*)d_in[9];
    const float* bv = (const float*)d_in[10];
    const float* Wo = (const float*)d_in[11];
    const float* bo = (const float*)d_in[12];
    float* out = (float*)d_out;

    cudaFuncSetAttribute(tc_qkv_kernel,   cudaFuncAttributeMaxDynamicSharedMemorySize, GEMM_SMEM);
    cudaFuncSetAttribute(tc_out_kernel,   cudaFuncAttributeMaxDynamicSharedMemorySize, GEMM_SMEM);
    cudaFuncSetAttribute(attn_mma_kernel, cudaFuncAttributeMaxDynamicSharedMemorySize, ATTN_SMEM);

    tc_qkv_kernel<<<dim3(D_MODEL/128, MTOT/128, 3), 256, GEMM_SMEM>>>(
        query, key, value, Wq, bq, Wk, bk, Wv, bv);
    scale_kernel<<<(MTOT + 255)/256, 256>>>(phi);
    attn_mma_kernel<<<dim3(TT/128, HEADS, BB), 256, ATTN_SMEM>>>();
    tc_out_kernel<<<dim3(D_MODEL/128, MTOT/128, 1), 256, GEMM_SMEM>>>(Wo, bo, out);
}

// round 9
// speedup vs baseline: 3.2930x; 1.1892x over previous
#include <cuda_runtime.h>
#include <cuda_bf16.h>
#include <cstdint>

#define D_MODEL 1024
#define HEADS   16
#define HD      64
#define BB      2
#define TT      2048
#define MTOT    (BB*TT)

// ---------------- GEMM config ----------------
#define GKC   32                   // K per chunk (32 bf16 = 64B row)
#define GNCH  (D_MODEL/GKC)        // 32
#define GOP   8192                 // op-half tile: 128 rows * 64B
#define GSTG  (4*GOP)              // Ahi,Alo,Whi,Wlo = 32768
#define GEMM_SMEM (3*GSTG)         // 3 stages = 98304

// ---------------- attention config ----------------
#define AQT   16384                // Q hi or lo tile: 128 rows * 128B
#define AKT   8192                 // K/V op tile: 64 rows * 128B
#define ASTG  (4*AKT)              // 32768
#define ATTN_SMEM (2*AQT + 3*ASTG) // 131072
#define NKT   (TT/64)              // 32

// -------- scratch (device globals; allocations forbidden) --------
__device__ __nv_bfloat16 g_xq_hi[(size_t)MTOT*D_MODEL], g_xq_lo[(size_t)MTOT*D_MODEL];
__device__ __nv_bfloat16 g_xk_hi[(size_t)MTOT*D_MODEL], g_xk_lo[(size_t)MTOT*D_MODEL];
__device__ __nv_bfloat16 g_xv_hi[(size_t)MTOT*D_MODEL], g_xv_lo[(size_t)MTOT*D_MODEL];
__device__ __nv_bfloat16 g_wq_hi[(size_t)D_MODEL*D_MODEL], g_wq_lo[(size_t)D_MODEL*D_MODEL];
__device__ __nv_bfloat16 g_wk_hi[(size_t)D_MODEL*D_MODEL], g_wk_lo[(size_t)D_MODEL*D_MODEL];
__device__ __nv_bfloat16 g_wv_hi[(size_t)D_MODEL*D_MODEL], g_wv_lo[(size_t)D_MODEL*D_MODEL];
__device__ __nv_bfloat16 g_wo_hi[(size_t)D_MODEL*D_MODEL], g_wo_lo[(size_t)D_MODEL*D_MODEL];
__device__ __nv_bfloat16 g_Qhi[(size_t)MTOT*D_MODEL], g_Qlo[(size_t)MTOT*D_MODEL];
__device__ __nv_bfloat16 g_Khi[(size_t)MTOT*D_MODEL], g_Klo[(size_t)MTOT*D_MODEL];
__device__ __nv_bfloat16 g_Vhi[(size_t)MTOT*D_MODEL], g_Vlo[(size_t)MTOT*D_MODEL];
__device__ __nv_bfloat16 g_Ahi[(size_t)MTOT*D_MODEL], g_Alo[(size_t)MTOT*D_MODEL];
__device__ float g_scl[MTOT];

// ---------------- helpers ----------------
__device__ __forceinline__ uint32_t smem_u32(const void* p) {
    uint32_t a;
    asm("{ .reg .u64 t; cvta.to.shared.u64 t, %1; cvt.u32.u64 %0, t; }" : "=r"(a) : "l"(p));
    return a;
}
__device__ __forceinline__ void ldsm4(uint32_t* r, uint32_t addr) {
    asm volatile("ldmatrix.sync.aligned.m8n8.x4.shared.b16 {%0,%1,%2,%3}, [%4];"
                 : "=r"(r[0]), "=r"(r[1]), "=r"(r[2]), "=r"(r[3]) : "r"(addr));
}
__device__ __forceinline__ void ldsm4t(uint32_t* r, uint32_t addr) {
    asm volatile("ldmatrix.sync.aligned.m8n8.x4.trans.shared.b16 {%0,%1,%2,%3}, [%4];"
                 : "=r"(r[0]), "=r"(r[1]), "=r"(r[2]), "=r"(r[3]) : "r"(addr));
}
__device__ __forceinline__ void mma_bf16(float* d, const uint32_t* a, const uint32_t* b) {
    asm volatile("mma.sync.aligned.m16n8k16.row.col.f32.bf16.bf16.f32 "
                 "{%0,%1,%2,%3}, {%4,%5,%6,%7}, {%8,%9}, {%0,%1,%2,%3};"
                 : "+f"(d[0]), "+f"(d[1]), "+f"(d[2]), "+f"(d[3])
                 : "r"(a[0]), "r"(a[1]), "r"(a[2]), "r"(a[3]), "r"(b[0]), "r"(b[1]));
}
__device__ __forceinline__ void cpa16(uint32_t dst, const void* src) {
    asm volatile("cp.async.cg.shared.global [%0], [%1], 16;" :: "r"(dst), "l"(src));
}
__device__ __forceinline__ void cp_commit() { asm volatile("cp.async.commit_group;"); }
template<int N> __device__ __forceinline__ void cp_wait() {
    asm volatile("cp.async.wait_group %0;" :: "n"(N));
}
__device__ __forceinline__ uint32_t bits(const __nv_bfloat162& h) {
    return *reinterpret_cast<const uint32_t*>(&h);
}
__device__ __forceinline__ void mk_hilo(uint32_t& hi, uint32_t& lo, float x, float y) {
    __nv_bfloat162 h = __floats2bfloat162_rn(x, y);
    float2 f = __bfloat1622float2(h);
    __nv_bfloat162 l = __floats2bfloat162_rn(x - f.x, y - f.y);
    hi = bits(h); lo = bits(l);
}

// ---------------------------------------------------------------------------
// fp32 -> split-bf16 conversion (one-shot, mem-bound)
// ---------------------------------------------------------------------------
__global__ void cvt_kernel(const float* __restrict__ src,
                           __nv_bfloat16* __restrict__ hi,
                           __nv_bfloat16* __restrict__ lo, int n4)
{
    int i = blockIdx.x * 256 + threadIdx.x;
    if (i < n4) {
        float4 x = ((const float4*)src)[i];
        uint32_t h0, l0, h1, l1;
        mk_hilo(h0, l0, x.x, x.y);
        mk_hilo(h1, l1, x.z, x.w);
        ((uint2*)hi)[i] = make_uint2(h0, h1);
        ((uint2*)lo)[i] = make_uint2(l0, l1);
    }
}

// ---------------------------------------------------------------------------
// HMMA split-bf16 GEMM: C = A @ W^T + bias, operands pre-split in gmem.
// 128x128 tile, 8 warps (2x4), 3-stage cp.async pipeline, occupancy 2.
// Smem op-half rows: 64B, swizzle ch' = ch ^ ((row>>1)&3) (16B chunks).
// ---------------------------------------------------------------------------
__device__ __forceinline__ void hmma_gemm_bf16(
    const __nv_bfloat16* __restrict__ Ahi, const __nv_bfloat16* __restrict__ Alo,
    const __nv_bfloat16* __restrict__ Whi, const __nv_bfloat16* __restrict__ Wlo,
    const float* __restrict__ bias,
    float* __restrict__ Cf, __nv_bfloat16* __restrict__ Chi, __nv_bfloat16* __restrict__ Clo)
{
    extern __shared__ char sm[];
    const int tid  = threadIdx.x;
    const int lane = tid & 31;
    const int wid  = tid >> 5;
    const int wm   = wid & 1;
    const int wn   = wid >> 1;
    const int m0   = blockIdx.y * 128;
    const int n0   = blockIdx.x * 128;
    const uint32_t sb = smem_u32(sm);

    float d[4][4][4];
#pragma unroll
    for (int mt = 0; mt < 4; mt++)
#pragma unroll
        for (int nt = 0; nt < 4; nt++)
#pragma unroll
            for (int e = 0; e < 4; e++) d[mt][nt][e] = 0.f;

    // loader: row0 = tid>>2 (0..63), ch = tid&3 fixed; rows {row0, row0+64}
    const int lrow = tid >> 2;
    const int lch  = tid & 3;
    const uint32_t ldst0 = (uint32_t)(lrow * 64 + ((lch ^ ((lrow >> 1) & 3)) << 4));
    const size_t aoff = (size_t)(m0 + lrow) * D_MODEL + lch * 8;
    const size_t woff = (size_t)(n0 + lrow) * D_MODEL + lch * 8;
    const size_t R64  = (size_t)64 * D_MODEL;

    auto ISSUE = [&](int c) {
        const uint32_t st = sb + (c % 3) * GSTG;
        const int k0 = c * GKC;
        cpa16(st + 0*GOP + ldst0,        Ahi + aoff + k0);
        cpa16(st + 0*GOP + ldst0 + 4096, Ahi + aoff + R64 + k0);
        cpa16(st + 1*GOP + ldst0,        Alo + aoff + k0);
        cpa16(st + 1*GOP + ldst0 + 4096, Alo + aoff + R64 + k0);
        cpa16(st + 2*GOP + ldst0,        Whi + woff + k0);
        cpa16(st + 2*GOP + ldst0 + 4096, Whi + woff + R64 + k0);
        cpa16(st + 3*GOP + ldst0,        Wlo + woff + k0);
        cpa16(st + 3*GOP + ldst0 + 4096, Wlo + woff + R64 + k0);
    };

    // fragment address precompute
    const int a_hi = lane >> 4;          // 16B column select
    const int b_c  = (lane >> 3) & 1;
    uint32_t a_rb[4], b_rb[2];
    int a_rm[4], b_rm[2];
#pragma unroll
    for (int mt = 0; mt < 4; mt++) {
        int row = wm*64 + mt*16 + (lane & 15);
        a_rb[mt] = row * 64; a_rm[mt] = (row >> 1) & 3;
    }
#pragma unroll
    for (int nh = 0; nh < 2; nh++) {
        int row = wn*32 + nh*16 + (lane & 7) + ((lane >> 4) << 3);
        b_rb[nh] = row * 64; b_rm[nh] = (row >> 1) & 3;
    }

    auto LD_A = [&](uint32_t opbase, int t, uint32_t af[4][4]) {
#pragma unroll
        for (int mt = 0; mt < 4; mt++)
            ldsm4(af[mt], opbase + a_rb[mt] + ((((t<<1)|a_hi) ^ a_rm[mt]) << 4));
    };
    auto LD_B = [&](uint32_t opbase, int t, uint32_t bf[4][2]) {
#pragma unroll
        for (int nh = 0; nh < 2; nh++) {
            uint32_t r[4];
            ldsm4(r, opbase + b_rb[nh] + ((((t<<1)|b_c) ^ b_rm[nh]) << 4));
            bf[nh*2+0][0] = r[0]; bf[nh*2+0][1] = r[1];
            bf[nh*2+1][0] = r[2]; bf[nh*2+1][1] = r[3];
        }
    };
    auto MMA16 = [&](const uint32_t af[4][4], const uint32_t bf[4][2]) {
#pragma unroll
        for (int mt = 0; mt < 4; mt++)
#pragma unroll
            for (int nt = 0; nt < 4; nt++)
                mma_bf16(d[mt][nt], af[mt], bf[nt]);
    };
    auto MMA_CHUNK = [&](int stg) {
        const uint32_t base = sb + stg * GSTG;
        uint32_t af[4][4], bf[4][2];
#pragma unroll
        for (int t = 0; t < 2; t++) {
            LD_A(base + 0*GOP, t, af);      // A hi
            LD_B(base + 2*GOP, t, bf);      // W hi
            MMA16(af, bf);                  // hh
            LD_B(base + 3*GOP, t, bf);      // W lo
            MMA16(af, bf);                  // hl
            LD_A(base + 1*GOP, t, af);      // A lo
            LD_B(base + 2*GOP, t, bf);      // W hi
            MMA16(af, bf);                  // lh
        }
    };

    // 3-stage pipeline, one sync per chunk
    ISSUE(0); cp_commit();
    ISSUE(1); cp_commit();
    for (int c = 0; c < GNCH; c++) {
        cp_wait<1>();
        __syncthreads();
        MMA_CHUNK(c % 3);
        if (c + 2 < GNCH) ISSUE(c + 2);   // stage (c+2)%3: last read at c-1, safe
        cp_commit();
    }

    // epilogue
    const int g = lane >> 2, tq = lane & 3;
#pragma unroll
    for (int mt = 0; mt < 4; mt++) {
#pragma unroll
        for (int nt = 0; nt < 4; nt++) {
            const int row = m0 + wm*64 + mt*16 + g;
            const int col = n0 + wn*32 + nt*8 + tq*2;
            const float b0 = bias[col], b1 = bias[col + 1];
            float c0 = d[mt][nt][0] + b0, c1 = d[mt][nt][1] + b1;
            float c2 = d[mt][nt][2] + b0, c3 = d[mt][nt][3] + b1;
            if (Cf) {
                *(float2*)&Cf[(size_t)row * D_MODEL + col]       = make_float2(c0, c1);
                *(float2*)&Cf[(size_t)(row + 8) * D_MODEL + col] = make_float2(c2, c3);
            } else {
                uint32_t h, l;
                mk_hilo(h, l, c0, c1);
                *(uint32_t*)&Chi[(size_t)row * D_MODEL + col] = h;
                *(uint32_t*)&Clo[(size_t)row * D_MODEL + col] = l;
                mk_hilo(h, l, c2, c3);
                *(uint32_t*)&Chi[(size_t)(row + 8) * D_MODEL + col] = h;
                *(uint32_t*)&Clo[(size_t)(row + 8) * D_MODEL + col] = l;
            }
        }
    }
}

__global__ __launch_bounds__(256, 2) void tc_qkv_kernel(
    const float* __restrict__ bq, const float* __restrict__ bk, const float* __restrict__ bv)
{
    if (blockIdx.z == 0)
        hmma_gemm_bf16(g_xq_hi, g_xq_lo, g_wq_hi, g_wq_lo, bq, nullptr, g_Qhi, g_Qlo);
    else if (blockIdx.z == 1)
        hmma_gemm_bf16(g_xk_hi, g_xk_lo, g_wk_hi, g_wk_lo, bk, nullptr, g_Khi, g_Klo);
    else
        hmma_gemm_bf16(g_xv_hi, g_xv_lo, g_wv_hi, g_wv_lo, bv, nullptr, g_Vhi, g_Vlo);
}

__global__ __launch_bounds__(256, 2) void tc_out_kernel(
    const float* __restrict__ bo, float* __restrict__ out)
{
    hmma_gemm_bf16(g_Ahi, g_Alo, g_wo_hi, g_wo_lo, bo, out, nullptr, nullptr);
}

// ---------------------------------------------------------------------------
// Per-query-token score scale (softmax shift-invariance kills additive terms)
// ---------------------------------------------------------------------------
__global__ void scale_kernel(const float* __restrict__ phi)
{
    int i = blockIdx.x * 256 + threadIdx.x;
    if (i < MTOT) {
        const float* p = phi + (size_t)i * 8;
        float s = 0.f;
#pragma unroll
        for (int f = 0; f < 8; f++) s += p[f];
        float ph = s * 0.125f;
        g_scl[i] = 1.0f / (8.0f * fmaxf(ph, 1e-6f));
    }
}

// ---------------------------------------------------------------------------
// HMMA flash attention, operands pre-split bf16 in gmem, cp.async loaders,
// 3-stage KV pipeline. 128B smem rows, swizzle ch' = ch ^ (row&7).
// ---------------------------------------------------------------------------
__global__ __launch_bounds__(256, 1) void attn_mma_kernel()
{
    extern __shared__ char sm[];
    const int tid  = threadIdx.x;
    const int lane = tid & 31;
    const int wid  = tid >> 5;
    const int b    = blockIdx.z, h = blockIdx.y;
    const int q0   = blockIdx.x * 128;
    const uint32_t sb  = smem_u32(sm);
    const uint32_t kvb = sb + 2*AQT;
    const size_t hoff = (size_t)h * HD;

    // ---- Q tile: cp.async copy of pre-split hi/lo ----
    {
        const int qrow = tid >> 3;         // 0..31
        const int qch  = tid & 7;
        const uint32_t qd = (uint32_t)(qrow * 128 + ((qch ^ (qrow & 7)) << 4));
        const size_t qsrc = (size_t)(b*TT + q0 + qrow) * D_MODEL + hoff + qch * 8;
        const size_t R32 = (size_t)32 * D_MODEL;
#pragma unroll
        for (int j = 0; j < 4; j++) {
            cpa16(sb + qd + j*4096,       g_Qhi + qsrc + j*R32);
            cpa16(sb + AQT + qd + j*4096, g_Qlo + qsrc + j*R32);
        }
        cp_commit();
    }

    // ---- KV loader: row0 = tid>>3 (0..31), ch = tid&7; rows {row0, row0+32} ----
    const int krow = tid >> 3;
    const int kch  = tid & 7;
    const uint32_t kd0 = (uint32_t)(krow * 128 + ((kch ^ (krow & 7)) << 4));
    const size_t koff = (size_t)(b*TT + krow) * D_MODEL + hoff + kch * 8;
    const size_t R32  = (size_t)32 * D_MODEL;
    const size_t TSTEP = (size_t)64 * D_MODEL;

    auto ISSUEKV = [&](int c) {
        const uint32_t st = kvb + (c % 3) * ASTG;
        const size_t s0 = koff + (size_t)c * TSTEP;
        cpa16(st + 0*AKT + kd0,        g_Khi + s0);
        cpa16(st + 0*AKT + kd0 + 4096, g_Khi + s0 + R32);
        cpa16(st + 1*AKT + kd0,        g_Klo + s0);
        cpa16(st + 1*AKT + kd0 + 4096, g_Klo + s0 + R32);
        cpa16(st + 2*AKT + kd0,        g_Vhi + s0);
        cpa16(st + 2*AKT + kd0 + 4096, g_Vhi + s0 + R32);
        cpa16(st + 3*AKT + kd0,        g_Vlo + s0);
        cpa16(st + 3*AKT + kd0 + 4096, g_Vlo + s0 + R32);
    };

    ISSUEKV(0); cp_commit();
    ISSUEKV(1); cp_commit();

    // ---- wait for Q (3 groups pending -> <=2 means Q done), load Q frags ----
    cp_wait<2>();
    __syncthreads();

    uint32_t qh[4][4], ql[4][4];
    {
        const int qr  = wid*16 + (lane & 15);
        const uint32_t qrb = (uint32_t)qr * 128;
        const int qrm = qr & 7;
        const int qhi = lane >> 4;
#pragma unroll
        for (int kc = 0; kc < 4; kc++) {
            ldsm4(qh[kc], sb       + qrb + ((((kc<<1)|qhi) ^ qrm) << 4));
            ldsm4(ql[kc], sb + AQT + qrb + ((((kc<<1)|qhi) ^ qrm) << 4));
        }
    }

    const int g = lane >> 2;
    const float rs0 = g_scl[b*TT + q0 + wid*16 + g];
    const float rs1 = g_scl[b*TT + q0 + wid*16 + g + 8];
    float m0 = -1e30f, m1 = -1e30f, l0 = 0.f, l1 = 0.f;
    float o[8][4];
#pragma unroll
    for (int dn = 0; dn < 8; dn++)
#pragma unroll
        for (int e = 0; e < 4; e++) o[dn][e] = 0.f;

    // fragment row precompute
    const int b_c = (lane >> 3) & 1;
    uint32_t k_rb[4]; int k_rm[4];
#pragma unroll
    for (int nq = 0; nq < 4; nq++) {
        int row = nq*16 + (lane & 7) + ((lane >> 4) << 3);
        k_rb[nq] = row * 128; k_rm[nq] = row & 7;
    }
    const int v_hi = lane >> 4;
    uint32_t v_rb[4]; int v_rm[4];
#pragma unroll
    for (int kc = 0; kc < 4; kc++) {
        int row = kc*16 + (lane & 15);
        v_rb[kc] = row * 128; v_rm[kc] = row & 7;
    }

    auto COMPUTE = [&](int stg) {
        const uint32_t kh = kvb + stg * ASTG;
        const uint32_t kl = kh + AKT;
        const uint32_t vh = kh + 2*AKT;
        const uint32_t vl = kh + 3*AKT;

        // ---- S = Q K^T (3-MMA split) ----
        float s[8][4];
#pragma unroll
        for (int nt = 0; nt < 8; nt++)
#pragma unroll
            for (int e = 0; e < 4; e++) s[nt][e] = 0.f;

#pragma unroll
        for (int kc = 0; kc < 4; kc++) {
#pragma unroll
            for (int nq = 0; nq < 4; nq++) {
                const uint32_t co = ((((kc<<1)|b_c) ^ k_rm[nq]) << 4);
                uint32_t r[4];
                ldsm4(r, kh + k_rb[nq] + co);
                uint32_t b0[2] = { r[0], r[1] }, b1[2] = { r[2], r[3] };
                mma_bf16(s[2*nq],   qh[kc], b0);
                mma_bf16(s[2*nq+1], qh[kc], b1);
                mma_bf16(s[2*nq],   ql[kc], b0);
                mma_bf16(s[2*nq+1], ql[kc], b1);
                ldsm4(r, kl + k_rb[nq] + co);
                uint32_t c0[2] = { r[0], r[1] }, c1[2] = { r[2], r[3] };
                mma_bf16(s[2*nq],   qh[kc], c0);
                mma_bf16(s[2*nq+1], qh[kc], c1);
            }
        }

        // ---- online softmax ----
        float tm0 = -1e30f, tm1 = -1e30f;
#pragma unroll
        for (int nt = 0; nt < 8; nt++) {
            s[nt][0] *= rs0; s[nt][1] *= rs0; s[nt][2] *= rs1; s[nt][3] *= rs1;
            tm0 = fmaxf(tm0, fmaxf(s[nt][0], s[nt][1]));
            tm1 = fmaxf(tm1, fmaxf(s[nt][2], s[nt][3]));
        }
        tm0 = fmaxf(tm0, __shfl_xor_sync(0xffffffffu, tm0, 1));
        tm0 = fmaxf(tm0, __shfl_xor_sync(0xffffffffu, tm0, 2));
        tm1 = fmaxf(tm1, __shfl_xor_sync(0xffffffffu, tm1, 1));
        tm1 = fmaxf(tm1, __shfl_xor_sync(0xffffffffu, tm1, 2));
        const float mn0 = fmaxf(m0, tm0), mn1 = fmaxf(m1, tm1);
        const float cr0 = __expf(m0 - mn0), cr1 = __expf(m1 - mn1);
        m0 = mn0; m1 = mn1;
        float ts0 = 0.f, ts1 = 0.f;
#pragma unroll
        for (int nt = 0; nt < 8; nt++) {
            s[nt][0] = __expf(s[nt][0] - mn0); ts0 += s[nt][0];
            s[nt][1] = __expf(s[nt][1] - mn0); ts0 += s[nt][1];
            s[nt][2] = __expf(s[nt][2] - mn1); ts1 += s[nt][2];
            s[nt][3] = __expf(s[nt][3] - mn1); ts1 += s[nt][3];
        }
        ts0 += __shfl_xor_sync(0xffffffffu, ts0, 1);
        ts0 += __shfl_xor_sync(0xffffffffu, ts0, 2);
        ts1 += __shfl_xor_sync(0xffffffffu, ts1, 1);
        ts1 += __shfl_xor_sync(0xffffffffu, ts1, 2);
        l0 = l0 * cr0 + ts0;
        l1 = l1 * cr1 + ts1;
#pragma unroll
        for (int dn = 0; dn < 8; dn++) {
            o[dn][0] *= cr0; o[dn][1] *= cr0; o[dn][2] *= cr1; o[dn][3] *= cr1;
        }

        // ---- O += P V (3-MMA split), V via trans ldmatrix ----
#pragma unroll
        for (int kc = 0; kc < 4; kc++) {
            uint32_t ah[4], al[4];
            mk_hilo(ah[0], al[0], s[2*kc][0],   s[2*kc][1]);
            mk_hilo(ah[1], al[1], s[2*kc][2],   s[2*kc][3]);
            mk_hilo(ah[2], al[2], s[2*kc+1][0], s[2*kc+1][1]);
            mk_hilo(ah[3], al[3], s[2*kc+1][2], s[2*kc+1][3]);
#pragma unroll
            for (int dq = 0; dq < 4; dq++) {
                const uint32_t co = ((((dq<<1)|v_hi) ^ v_rm[kc]) << 4);
                uint32_t r[4];
                ldsm4t(r, vh + v_rb[kc] + co);
                uint32_t b0[2] = { r[0], r[1] }, b1[2] = { r[2], r[3] };
                mma_bf16(o[2*dq],   ah, b0);
                mma_bf16(o[2*dq+1], ah, b1);
                mma_bf16(o[2*dq],   al, b0);
                mma_bf16(o[2*dq+1], al, b1);
                ldsm4t(r, vl + v_rb[kc] + co);
                uint32_t c0[2] = { r[0], r[1] }, c1[2] = { r[2], r[3] };
                mma_bf16(o[2*dq],   ah, c0);
                mma_bf16(o[2*dq+1], ah, c1);
            }
        }
    };

    // ---- main loop: 3-stage, one sync per tile ----
    for (int c = 0; c < NKT; c++) {
        cp_wait<1>();
        __syncthreads();
        COMPUTE(c % 3);
        if (c + 2 < NKT) ISSUEKV(c + 2);
        cp_commit();
    }

    // ---- normalize & write split-bf16 head output ----
    const float inv0 = 1.0f / l0, inv1 = 1.0f / l1;
    const int t2 = (lane & 3) * 2;
    const size_t row0 = (size_t)(b*TT + q0 + wid*16 + g);
#pragma unroll
    for (int dn = 0; dn < 8; dn++) {
        uint32_t hh, ll;
        mk_hilo(hh, ll, o[dn][0]*inv0, o[dn][1]*inv0);
        *(uint32_t*)&g_Ahi[row0 * D_MODEL + hoff + dn*8 + t2] = hh;
        *(uint32_t*)&g_Alo[row0 * D_MODEL + hoff + dn*8 + t2] = ll;
        mk_hilo(hh, ll, o[dn][2]*inv1, o[dn][3]*inv1);
        *(uint32_t*)&g_Ahi[(row0 + 8) * D_MODEL + hoff + dn*8 + t2] = hh;
        *(uint32_t*)&g_Alo[(row0 + 8) * D_MODEL + hoff + dn*8 + t2] = ll;
    }
}

// ---------------------------------------------------------------------------
extern "C" void kernel_launch(void* const* d_in, const int* in_sizes, int n_in,
                              void* d_out, int out_size)
{
    const float* query = (const float*)d_in[0];
    const float* key   = (const float*)d_in[1];
    const float* value = (const float*)d_in[2];
    const float* phi   = (const float*)d_in[3];
    // d_in[4] logvar, d_in[13] w_sigma, d_in[14] w_phi: cancel under softmax
    const float* Wq = (const float*)d_in[5];
    const float* bq = (const float*)d_in[6];
    const float* Wk = (const float*)d_in[7];
    const float* bk = (const float*)d_in[8];
    const float* Wv = (const float*)d_in[9];
    const float* bv = (const float*)d_in[10];
    const float* Wo = (const float*)d_in[11];
    const float* bo = (const float*)d_in[12];
    float* out = (float*)d_out;

    cudaFuncSetAttribute(tc_qkv_kernel,   cudaFuncAttributeMaxDynamicSharedMemorySize, GEMM_SMEM);
    cudaFuncSetAttribute(tc_out_kernel,   cudaFuncAttributeMaxDynamicSharedMemorySize, GEMM_SMEM);
    cudaFuncSetAttribute(attn_mma_kernel, cudaFuncAttributeMaxDynamicSharedMemorySize, ATTN_SMEM);

    // resolve device-global buffer addresses (host side, graph-capturable)
    static __nv_bfloat16 *xq_hi=nullptr, *xq_lo, *xk_hi, *xk_lo, *xv_hi, *xv_lo;
    static __nv_bfloat16 *wq_hi, *wq_lo, *wk_hi, *wk_lo, *wv_hi, *wv_lo, *wo_hi, *wo_lo;
    if (!xq_hi) {
        cudaGetSymbolAddress((void**)&xq_hi, g_xq_hi);
        cudaGetSymbolAddress((void**)&xq_lo, g_xq_lo);
        cudaGetSymbolAddress((void**)&xk_hi, g_xk_hi);
        cudaGetSymbolAddress((void**)&xk_lo, g_xk_lo);
        cudaGetSymbolAddress((void**)&xv_hi, g_xv_hi);
        cudaGetSymbolAddress((void**)&xv_lo, g_xv_lo);
        cudaGetSymbolAddress((void**)&wq_hi, g_wq_hi);
        cudaGetSymbolAddress((void**)&wq_lo, g_wq_lo);
        cudaGetSymbolAddress((void**)&wk_hi, g_wk_hi);
        cudaGetSymbolAddress((void**)&wk_lo, g_wk_lo);
        cudaGetSymbolAddress((void**)&wv_hi, g_wv_hi);
        cudaGetSymbolAddress((void**)&wv_lo, g_wv_lo);
        cudaGetSymbolAddress((void**)&wo_hi, g_wo_hi);
        cudaGetSymbolAddress((void**)&wo_lo, g_wo_lo);
    }

    const int n4_act = MTOT * D_MODEL / 4;      // 1048576
    const int n4_w   = D_MODEL * D_MODEL / 4;   // 262144

    cvt_kernel<<<n4_act/256, 256>>>(query, xq_hi, xq_lo, n4_act);
    cvt_kernel<<<n4_act/256, 256>>>(key,   xk_hi, xk_lo, n4_act);
    cvt_kernel<<<n4_act/256, 256>>>(value, xv_hi, xv_lo, n4_act);
    cvt_kernel<<<n4_w/256, 256>>>(Wq, wq_hi, wq_lo, n4_w);
    cvt_kernel<<<n4_w/256, 256>>>(Wk, wk_hi, wk_lo, n4_w);
    cvt_kernel<<<n4_w/256, 256>>>(Wv, wv_hi, wv_lo, n4_w);
    cvt_kernel<<<n4_w/256, 256>>>(Wo, wo_hi, wo_lo, n4_w);

    scale_kernel<<<(MTOT + 255)/256, 256>>>(phi);
    tc_qkv_kernel<<<dim3(D_MODEL/128, MTOT/128, 3), 256, GEMM_SMEM>>>(bq, bk, bv);
    attn_mma_kernel<<<dim3(TT/128, HEADS, BB), 256, ATTN_SMEM>>>();
    tc_out_kernel<<<dim3(D_MODEL/128, MTOT/128, 1), 256, GEMM_SMEM>>>(bo, out);
}